// round 12
// baseline (speedup 1.0000x reference)
#include <cuda_runtime.h>
#include <math.h>

#define N_NODES 20000
#define N_EDGES 400000
#define KT 2048
typedef unsigned long long ull;

// ---------------- device globals --------------------------------------------
__device__ float g_S[(size_t)N_NODES * KT];      // per-node T rows
__device__ float g_Hsum[(size_t)N_NODES * 128];  // per-node hid sums
__device__ float g_HsJ[N_NODES * 16];            // per-node sum of h[src]
__device__ float g_hid[(size_t)N_EDGES * 128];   // hid in DST-SORTED order
__device__ float g_B[4096 * 16];                 // permuted W2
__device__ float g_h0[N_NODES * 16];
__device__ float g_h1[N_NODES * 16];
__device__ int   g_deg[N_NODES];
__device__ int   g_cursor[N_NODES];
__device__ int   g_off[N_NODES + 1];
__device__ int2  g_es[N_EDGES];                  // (edge id, src) sorted by dst

__device__ __forceinline__ float* pick_buf(int s, float* ext) {
    if (s == 0) return g_h0;
    if (s == 1) return g_h1;
    return ext;
}
__device__ __forceinline__ const float* pick_cbuf(int s, const float* ext) {
    if (s == 0) return g_h0;
    if (s == 1) return g_h1;
    return ext;
}

// ---------------- f32x2 helpers ----------------------------------------------
__device__ __forceinline__ ull pack2(float a, float b) {
    ull r; asm("mov.b64 %0, {%1, %2};" : "=l"(r) : "f"(a), "f"(b)); return r;
}
__device__ __forceinline__ void unpack2(ull v, float& a, float& b) {
    asm("mov.b64 {%0, %1}, %2;" : "=f"(a), "=f"(b) : "l"(v));
}
__device__ __forceinline__ ull fma2(ull a, ull b, ull c) {
    ull d; asm("fma.rn.f32x2 %0, %1, %2, %3;" : "=l"(d) : "l"(a), "l"(b), "l"(c));
    return d;
}
__device__ __forceinline__ ull add2(ull a, ull b) {
    ull d; asm("add.rn.f32x2 %0, %1, %2;" : "=l"(d) : "l"(a), "l"(b)); return d;
}

// ---------------- launch 0: fused front (count/embed/edge-embed/ei) ----------
#define COUNT_BLOCKS 1563
#define EMBED_BLOCKS 79
#define EE_BLOCKS 1563
#define EIC_BLOCKS 3125
#define FRONT_BLOCKS (COUNT_BLOCKS + EMBED_BLOCKS + EE_BLOCKS + EIC_BLOCKS)

__global__ void __launch_bounds__(256) k_front(
    const int* __restrict__ ei, const float* __restrict__ x,
    const float* __restrict__ Wn, const float* __restrict__ bn,
    const float* __restrict__ ea, const float* __restrict__ We,
    const float* __restrict__ be,
    float* __restrict__ ee_out, float* __restrict__ lsm_out,
    float* __restrict__ ei_out, int n_ee, int n_lsm, int n_ei) {
    int b = blockIdx.x;
    int tid = threadIdx.x;
    if (b < COUNT_BLOCKS) {
        int e = b * 256 + tid;
        if (e < N_EDGES) atomicAdd(&g_deg[ei[N_EDGES + e]], 1);
    } else if (b < COUNT_BLOCKS + EMBED_BLOCKS) {
        __shared__ float sW[256];
        __shared__ float sb[16];
        sW[tid] = Wn[tid];
        if (tid < 16) sb[tid] = bn[tid];
        __syncthreads();
        int n = (b - COUNT_BLOCKS) * 256 + tid;
        if (n >= N_NODES) return;
        float xi[16];
        const float4* xp = (const float4*)(x + (size_t)n * 16);
#pragma unroll
        for (int q = 0; q < 4; q++) {
            float4 v = xp[q];
            xi[4*q] = v.x; xi[4*q+1] = v.y; xi[4*q+2] = v.z; xi[4*q+3] = v.w;
        }
        float o[16];
#pragma unroll
        for (int d = 0; d < 16; d++) {
            float acc = sb[d];
#pragma unroll
            for (int k = 0; k < 16; k++) acc = fmaf(xi[k], sW[k*16+d], acc);
            o[d] = fmaxf(acc, 0.f);
        }
        float4* op = (float4*)(g_h0 + (size_t)n * 16);
#pragma unroll
        for (int q = 0; q < 4; q++)
            op[q] = make_float4(o[4*q], o[4*q+1], o[4*q+2], o[4*q+3]);
    } else if (b < COUNT_BLOCKS + EMBED_BLOCKS + EE_BLOCKS) {
        __shared__ float sW[256];
        __shared__ float sb[16];
        sW[tid] = We[tid];
        if (tid < 16) sb[tid] = be[tid];
        __syncthreads();
        int e = (b - COUNT_BLOCKS - EMBED_BLOCKS) * 256 + tid;
        if (e >= N_EDGES) return;
        float xi[16];
        const float4* xp = (const float4*)(ea + (size_t)e * 16);
#pragma unroll
        for (int q = 0; q < 4; q++) {
            float4 v = xp[q];
            xi[4*q] = v.x; xi[4*q+1] = v.y; xi[4*q+2] = v.z; xi[4*q+3] = v.w;
        }
        float v[16];
        float m = -1e30f;
#pragma unroll
        for (int d = 0; d < 16; d++) {
            float acc = sb[d];
#pragma unroll
            for (int k = 0; k < 16; k++) acc = fmaf(xi[k], sW[k*16+d], acc);
            v[d] = fmaxf(acc, 0.f);
            m = fmaxf(m, v[d]);
        }
        float s = 0.f;
#pragma unroll
        for (int d = 0; d < 16; d++) s += expf(v[d] - m);
        float ls = m + logf(s);
        if (e < n_ee) {
            float4* eo = (float4*)(ee_out + (size_t)e * 16);
#pragma unroll
            for (int q = 0; q < 4; q++)
                eo[q] = make_float4(v[4*q], v[4*q+1], v[4*q+2], v[4*q+3]);
        }
        if (e < n_lsm) {
            float4* lo = (float4*)(lsm_out + (size_t)e * 16);
#pragma unroll
            for (int q = 0; q < 4; q++)
                lo[q] = make_float4(v[4*q] - ls, v[4*q+1] - ls,
                                    v[4*q+2] - ls, v[4*q+3] - ls);
        }
    } else {
        int i = (b - COUNT_BLOCKS - EMBED_BLOCKS - EE_BLOCKS) * 256 + tid;
        if (i < n_ei) ei_out[i] = (float)ei[i];
    }
}

// ---------------- launch 1: prefix scan --------------------------------------
__global__ void __launch_bounds__(1024) k_scan() {
    __shared__ int sm[1024];
    int t = threadIdx.x;
    int base = t * 20;
    int vals[20];
    int local = 0;
#pragma unroll
    for (int i = 0; i < 20; i++) {
        int idx = base + i;
        vals[i] = (idx < N_NODES) ? g_deg[idx] : 0;
        local += vals[i];
    }
    sm[t] = local;
    __syncthreads();
    for (int off = 1; off < 1024; off <<= 1) {
        int v = (t >= off) ? sm[t - off] : 0;
        __syncthreads();
        sm[t] += v;
        __syncthreads();
    }
    int run = sm[t] - local;
#pragma unroll
    for (int i = 0; i < 20; i++) {
        int idx = base + i;
        if (idx < N_NODES) { g_off[idx] = run; run += vals[i]; g_cursor[idx] = 0; }
    }
    if (t == 0) g_off[N_NODES] = N_EDGES;
}

// ---------------- launch 2: fill sorted edge list -----------------------------
__global__ void k_fill(const int* __restrict__ ei) {
    int e = blockIdx.x * blockDim.x + threadIdx.x;
    if (e < N_EDGES) {
        int d = ei[N_EDGES + e];
        int pos = g_off[d] + atomicAdd(&g_cursor[d], 1);
        g_es[pos] = make_int2(e, ei[e]);
    }
    if (e < N_NODES) g_deg[e] = 0;
}

// ---------------- launch 3: hid (iterate sorted positions) + B build ---------
// Gather ea rows (64 B scattered reads), write g_hid perfectly sequentially.
#define HID_BLOCKS 6250
#define B_BLOCKS 256
__global__ void __launch_bounds__(256) k_prep2(
    const float* __restrict__ ea,
    const float* __restrict__ W1, const float* __restrict__ b1,
    const float* __restrict__ W2) {
    int b = blockIdx.x;
    int tid = threadIdx.x;
    if (b < HID_BLOCKS) {
        __shared__ float sEA[64 * 17];
        __shared__ float sW1[16 * 128];
        __shared__ float sB1[128];
        __shared__ int   sE[64];
        int p0 = b * 64;                       // sorted-position tile
        if (tid < 64) sE[tid] = g_es[p0 + tid].x;
        for (int idx = tid; idx < 2048; idx += 256) sW1[idx] = W1[idx];
        if (tid < 128) sB1[tid] = b1[tid];
        __syncthreads();
        // gather ea rows: 16 lanes per edge row -> 64B contiguous per half-warp
        for (int idx = tid; idx < 64 * 16; idx += 256) {
            int e = idx >> 4, k = idx & 15;
            sEA[e*17 + k] = ea[(size_t)sE[e] * 16 + k];
        }
        __syncthreads();
        int el = tid >> 2;                     // local position
        int p  = tid & 3;                      // output quarter
        float a[16];
#pragma unroll
        for (int k = 0; k < 16; k++) a[k] = sEA[el*17 + k];
        float* outp = g_hid + (size_t)(p0 + el) * 128 + p * 32;   // sequential!
#pragma unroll
        for (int uu = 0; uu < 32; uu += 4) {
            int ub = p*32 + uu;
            float c0 = sB1[ub+0], c1 = sB1[ub+1], c2 = sB1[ub+2], c3 = sB1[ub+3];
#pragma unroll
            for (int k = 0; k < 16; k++) {
                float av = a[k];
                const float* wr = &sW1[k*128 + ub];
                c0 = fmaf(av, wr[0], c0);
                c1 = fmaf(av, wr[1], c1);
                c2 = fmaf(av, wr[2], c2);
                c3 = fmaf(av, wr[3], c3);
            }
            *(float4*)(outp + uu) = make_float4(fmaxf(c0, 0.f), fmaxf(c1, 0.f),
                                                fmaxf(c2, 0.f), fmaxf(c3, 0.f));
        }
    } else {
        int idx = (b - HID_BLOCKS) * 256 + tid;
        int kj = idx >> 4, d = idx & 15;
        float v;
        if (kj < 2048) {
            int k = kj >> 4, j = kj & 15;
            v = W2[(size_t)k * 512 + (16 + j) * 16 + d];
        } else {
            int m = kj - 2048;
            int k = m >> 4, r = m & 15;
            v = W2[(size_t)k * 512 + r * 16 + d];
        }
        g_B[idx] = v;
    }
}

// ---------------- edge pass: streaming hid, pipelined -------------------------
#define EP_SMEM (8 * 32 * 68 * 4)
__global__ void __launch_bounds__(256, 2) k_edge_pass(int sin) {
    extern __shared__ float st[];
    const float* hin = (sin == 0) ? g_h0 : g_h1;
    int tid = threadIdx.x, wid = tid >> 5, l = tid & 31;
    int n = blockIdx.x * 8 + wid;

    int start = g_off[n], end = g_off[n + 1];

    ull T[4][8];
#pragma unroll
    for (int kk = 0; kk < 4; kk++)
#pragma unroll
        for (int q = 0; q < 8; q++) T[kk][q] = 0ull;
    ull Hs[8];
#pragma unroll
    for (int q = 0; q < 8; q++) Hs[q] = 0ull;
    float hs0 = 0.f, hs1 = 0.f, hs2 = 0.f, hs3 = 0.f;

    if (start < end) {
        int last = end - 1;
        float4 hidC = *(const float4*)(g_hid + (size_t)start * 128 + 4*l);
        int2 esC = g_es[start];
        const ulonglong2* hp = (const ulonglong2*)(hin + (size_t)esC.y * 16);
        ulonglong2 ha = hp[0], hb = hp[1], hc = hp[2], hd = hp[3];
        ull hC[8] = {ha.x, ha.y, hb.x, hb.y, hc.x, hc.y, hd.x, hd.y};

        for (int pos = start; pos < end; pos++) {
            int pn = pos + 1 <= last ? pos + 1 : last;
            float4 hidN = *(const float4*)(g_hid + (size_t)pn * 128 + 4*l);
            int2 esN = g_es[pn];
            const ulonglong2* hp2 = (const ulonglong2*)(hin + (size_t)esN.y * 16);
            ulonglong2 na = hp2[0], nb = hp2[1], nc = hp2[2], nd = hp2[3];
            float4 hd4 = hidC;
#pragma unroll
            for (int q = 0; q < 8; q++) Hs[q] = add2(Hs[q], hC[q]);
            hs0 += hd4.x; hs1 += hd4.y; hs2 += hd4.z; hs3 += hd4.w;
            ull p0 = pack2(hd4.x, hd4.x), pq1 = pack2(hd4.y, hd4.y);
            ull pq2 = pack2(hd4.z, hd4.z), pq3 = pack2(hd4.w, hd4.w);
#pragma unroll
            for (int q = 0; q < 8; q++) {
                T[0][q] = fma2(p0, hC[q], T[0][q]);
                T[1][q] = fma2(pq1, hC[q], T[1][q]);
                T[2][q] = fma2(pq2, hC[q], T[2][q]);
                T[3][q] = fma2(pq3, hC[q], T[3][q]);
            }
            hidC = hidN;
            hC[0] = na.x; hC[1] = na.y; hC[2] = nb.x; hC[3] = nb.y;
            hC[4] = nc.x; hC[5] = nc.y; hC[6] = nd.x; hC[7] = nd.y;
        }
    }

    // write T via warp-local smem transpose (coalesced)
    float* W = st + wid * (32 * 68) + l * 68;
#pragma unroll
    for (int kk = 0; kk < 4; kk++) {
        float t[16];
#pragma unroll
        for (int q = 0; q < 8; q++) unpack2(T[kk][q], t[2*q], t[2*q+1]);
#pragma unroll
        for (int f = 0; f < 4; f++)
            *(float4*)&W[kk*16 + 4*f] = make_float4(t[4*f], t[4*f+1], t[4*f+2], t[4*f+3]);
    }
    __syncwarp();
    float* Wbase = st + wid * (32 * 68);
    float* Trow = g_S + (size_t)n * KT;
#pragma unroll
    for (int s = 0; s < 16; s++) {
        int idx = s * 128 + 4 * l;
        float4 v = *(float4*)&Wbase[(idx >> 6) * 68 + (idx & 63)];
        *(float4*)&Trow[idx] = v;
    }
    *(float4*)&g_Hsum[(size_t)n * 128 + 4*l] = make_float4(hs0, hs1, hs2, hs3);
    if (l == 0) {
#pragma unroll
        for (int q = 0; q < 8; q++) {
            float a, b; unpack2(Hs[q], a, b);
            g_HsJ[n * 16 + 2*q]     = a;
            g_HsJ[n * 16 + 2*q + 1] = b;
        }
    }
}

// ---------------- epilogue: seed hout with non-GEMM terms --------------------
__global__ void k_epi(int sin, int sout, float* ext,
                      const float* __restrict__ root,
                      const float* __restrict__ b2,
                      const float* __restrict__ bias) {
    __shared__ float sR[256];
    __shared__ float sB2[512];
    __shared__ float sBi[16];
    const float* hin = pick_cbuf(sin, ext);
    float* hout = pick_buf(sout, ext);
    int tid = threadIdx.x;
    sR[tid] = root[tid];
    sB2[tid] = b2[tid];
    sB2[256 + tid] = b2[256 + tid];
    if (tid < 16) sBi[tid] = bias[tid];
    __syncthreads();
    int n = blockIdx.x * 256 + tid;
    if (n >= N_NODES) return;
    float h[16], hs[16];
    const float4* hp = (const float4*)(hin + (size_t)n * 16);
    const float4* sp = (const float4*)(g_HsJ + (size_t)n * 16);
#pragma unroll
    for (int q = 0; q < 4; q++) {
        float4 a = hp[q]; h[4*q] = a.x; h[4*q+1] = a.y; h[4*q+2] = a.z; h[4*q+3] = a.w;
        float4 b = sp[q]; hs[4*q] = b.x; hs[4*q+1] = b.y; hs[4*q+2] = b.z; hs[4*q+3] = b.w;
    }
    float dg = (float)(g_off[n+1] - g_off[n]);
    float o[16];
#pragma unroll
    for (int d = 0; d < 16; d++) o[d] = sBi[d];
#pragma unroll
    for (int r = 0; r < 16; r++) {
        float hr = h[r], hdg = h[r] * dg, hj = hs[r];
#pragma unroll
        for (int d = 0; d < 16; d++) {
            o[d] = fmaf(hr, sR[r*16+d], o[d]);
            o[d] = fmaf(hdg, sB2[r*16+d], o[d]);
            o[d] = fmaf(hj, sB2[256 + r*16+d], o[d]);
        }
    }
    float4* op = (float4*)(hout + (size_t)n * 16);
#pragma unroll
    for (int q = 0; q < 4; q++)
        op[q] = make_float4(o[4*q], o[4*q+1], o[4*q+2], o[4*q+3]);
}

// ---------------- GEMM: hout += [T | synth(Hsum⊗h)] @ B ----------------------
#define GT 256
#define SA_P 129
__global__ void __launch_bounds__(GT) k_gemm(int sin, int sout, float* ext) {
    __shared__ __align__(16) float sA[64 * SA_P];
    __shared__ __align__(16) float sB[64 * 16];
    const float* hin = pick_cbuf(sin, ext);
    float* hout = pick_buf(sout, ext);
    int tid = threadIdx.x;
    int n0 = blockIdx.x * 128;
    int ks = blockIdx.y;
    int nn = tid & 127, half = tid >> 7;
    ull acc[4] = {0ull, 0ull, 0ull, 0ull};

    float4 r[8];
    float4 rb;
    auto load_chunk = [&](int c) {
        int k0 = c * 64;
#pragma unroll
        for (int j = 0; j < 8; j++) {
            int i = tid + j * 256;
            int an = i >> 4, q = i & 15;
            int gn = n0 + an;
            float4 v = make_float4(0.f, 0.f, 0.f, 0.f);
            if (gn < N_NODES) {
                if (c < 32) {
                    v = *(const float4*)(g_S + (size_t)gn * KT + k0 + 4*q);
                } else {
                    int m = k0 - 2048 + 4*q;
                    float hsv = g_Hsum[(size_t)gn * 128 + (m >> 4)];
                    float4 h4 = ((const float4*)(hin + (size_t)gn * 16))[(m & 15) >> 2];
                    v = make_float4(hsv*h4.x, hsv*h4.y, hsv*h4.z, hsv*h4.w);
                }
            }
            r[j] = v;
        }
        rb = ((const float4*)(g_B + (size_t)k0 * 16))[tid];
    };

    load_chunk(ks * 8);
    for (int ci = 0; ci < 8; ci++) {
        __syncthreads();
#pragma unroll
        for (int j = 0; j < 8; j++) {
            int i = tid + j * 256;
            int an = i >> 4, q = i & 15;
            sA[(4*q + 0) * SA_P + an] = r[j].x;
            sA[(4*q + 1) * SA_P + an] = r[j].y;
            sA[(4*q + 2) * SA_P + an] = r[j].z;
            sA[(4*q + 3) * SA_P + an] = r[j].w;
        }
        ((float4*)sB)[tid] = rb;
        __syncthreads();
        if (ci < 7) load_chunk(ks * 8 + ci + 1);
#pragma unroll 8
        for (int k = 0; k < 64; k++) {
            float a = sA[k * SA_P + nn];
            ull a2 = pack2(a, a);
            ulonglong2 b01 = *(const ulonglong2*)&sB[k * 16 + 8 * half];
            ulonglong2 b23 = *(const ulonglong2*)&sB[k * 16 + 8 * half + 4];
            acc[0] = fma2(a2, b01.x, acc[0]);
            acc[1] = fma2(a2, b01.y, acc[1]);
            acc[2] = fma2(a2, b23.x, acc[2]);
            acc[3] = fma2(a2, b23.y, acc[3]);
        }
    }

    int n = n0 + nn;
    if (n < N_NODES) {
        float o[8];
        unpack2(acc[0], o[0], o[1]);
        unpack2(acc[1], o[2], o[3]);
        unpack2(acc[2], o[4], o[5]);
        unpack2(acc[3], o[6], o[7]);
        float* dst = hout + (size_t)n * 16 + 8 * half;
#pragma unroll
        for (int j = 0; j < 8; j++) atomicAdd(dst + j, o[j]);
    }
}

// ---------------- launch -------------------------------------------------------
extern "C" void kernel_launch(void* const* d_in, const int* in_sizes, int n_in,
                              void* d_out, int out_size) {
    const float* x     = (const float*)d_in[0];
    const int*   ei    = (const int*)d_in[1];
    const float* ea    = (const float*)d_in[2];
    const float* Wn    = (const float*)d_in[3];
    const float* bn    = (const float*)d_in[4];
    const float* We    = (const float*)d_in[5];
    const float* be    = (const float*)d_in[6];
    const float* W1    = (const float*)d_in[7];
    const float* b1    = (const float*)d_in[8];
    const float* W2    = (const float*)d_in[9];
    const float* b2    = (const float*)d_in[10];
    const float* root1 = (const float*)d_in[11];
    const float* bias1 = (const float*)d_in[12];
    const float* root2 = (const float*)d_in[13];
    const float* bias2 = (const float*)d_in[14];

    float* out = (float*)d_out;
    size_t cap = (size_t)out_size;

    size_t ei_slots = (cap == 13120000) ? 0 : 2ull * N_EDGES;
    size_t off_h   = 0;
    size_t off_ei  = off_h + (size_t)N_NODES * 16;
    size_t off_ee  = off_ei + ei_slots;
    size_t off_lsm = off_ee + (size_t)N_EDGES * 16;
    auto avail = [&](size_t off) -> size_t { return off < cap ? cap - off : 0; };

    float* out_h   = out + off_h;
    float* out_ei  = out + off_ei;
    float* out_ee  = out + off_ee;
    float* out_lsm = out + off_lsm;

    bool h_fits = avail(off_h) >= (size_t)N_NODES * 16;
    int  n_ei   = ei_slots ? (int)min((size_t)(2 * N_EDGES), avail(off_ei)) : 0;
    int  n_ee   = (int)min((size_t)N_EDGES, avail(off_ee) / 16);
    int  n_lsm  = (int)min((size_t)N_EDGES, avail(off_lsm) / 16);
    int  sout2  = h_fits ? 2 : 0;

    cudaFuncSetAttribute(k_edge_pass, cudaFuncAttributeMaxDynamicSharedMemorySize,
                         EP_SMEM);

    // 0: fused front: degree count + node embed + edge embed/lsm + ei copy
    k_front<<<FRONT_BLOCKS, 256>>>(ei, x, Wn, bn, ea, We, be,
                                   out_ee, out_lsm, out_ei, n_ee, n_lsm, n_ei);
    // 1: prefix scan (re-zeros g_cursor)
    k_scan<<<1, 1024>>>();
    // 2: fill sorted edge list (re-zeros g_deg)
    k_fill<<<COUNT_BLOCKS, 256>>>(ei);
    // 3: hid (sorted positions, sequential writes) + B build   [profiled]
    k_prep2<<<HID_BLOCKS + B_BLOCKS, 256>>>(ea, W1, b1, W2);

    dim3 gg((N_NODES + 127) / 128, 8);
    // layer 1
    k_edge_pass<<<N_NODES / 8, 256, EP_SMEM>>>(0);
    k_epi<<<(N_NODES + 255) / 256, 256>>>(0, 1, out_h, root1, b2, bias1);
    k_gemm<<<gg, GT>>>(0, 1, out_h);
    // layer 2
    k_edge_pass<<<N_NODES / 8, 256, EP_SMEM>>>(1);
    k_epi<<<(N_NODES + 255) / 256, 256>>>(1, sout2, out_h, root2, b2, bias2);
    k_gemm<<<gg, GT>>>(1, sout2, out_h);
}

// round 13
// speedup vs baseline: 1.3545x; 1.3545x over previous
#include <cuda_runtime.h>
#include <math.h>

#define N_NODES 20000
#define N_EDGES 400000
#define KT 2048
typedef unsigned long long ull;

// ---------------- device globals --------------------------------------------
__device__ float g_S[(size_t)N_NODES * KT];      // per-node T rows
__device__ float g_Hsum[(size_t)N_NODES * 128];  // per-node hid sums
__device__ float g_HsJ[N_NODES * 16];            // per-node sum of h[src]
__device__ float g_hid[(size_t)N_EDGES * 128];   // hid in DST-SORTED order
__device__ float g_B[4096 * 16];                 // permuted W2
__device__ float g_h0[N_NODES * 16];
__device__ float g_h1[N_NODES * 16];
__device__ int   g_deg[N_NODES];
__device__ int   g_cursor[N_NODES];
__device__ int   g_off[N_NODES + 1];
__device__ int2  g_es[N_EDGES];                  // (edge id, src) sorted by dst

__device__ __forceinline__ float* pick_buf(int s, float* ext) {
    if (s == 0) return g_h0;
    if (s == 1) return g_h1;
    return ext;
}
__device__ __forceinline__ const float* pick_cbuf(int s, const float* ext) {
    if (s == 0) return g_h0;
    if (s == 1) return g_h1;
    return ext;
}

// ---------------- f32x2 helpers ----------------------------------------------
__device__ __forceinline__ ull pack2(float a, float b) {
    ull r; asm("mov.b64 %0, {%1, %2};" : "=l"(r) : "f"(a), "f"(b)); return r;
}
__device__ __forceinline__ void unpack2(ull v, float& a, float& b) {
    asm("mov.b64 {%0, %1}, %2;" : "=f"(a), "=f"(b) : "l"(v));
}
__device__ __forceinline__ ull fma2(ull a, ull b, ull c) {
    ull d; asm("fma.rn.f32x2 %0, %1, %2, %3;" : "=l"(d) : "l"(a), "l"(b), "l"(c));
    return d;
}
__device__ __forceinline__ ull add2(ull a, ull b) {
    ull d; asm("add.rn.f32x2 %0, %1, %2;" : "=l"(d) : "l"(a), "l"(b)); return d;
}

// ---------------- launch 0: fused front (count/embed/edge-embed/ei) ----------
#define COUNT_BLOCKS 1563
#define EMBED_BLOCKS 79
#define EE_BLOCKS 1563
#define EIC_BLOCKS 3125
#define FRONT_BLOCKS (COUNT_BLOCKS + EMBED_BLOCKS + EE_BLOCKS + EIC_BLOCKS)

__global__ void __launch_bounds__(256) k_front(
    const int* __restrict__ ei, const float* __restrict__ x,
    const float* __restrict__ Wn, const float* __restrict__ bn,
    const float* __restrict__ ea, const float* __restrict__ We,
    const float* __restrict__ be,
    float* __restrict__ ee_out, float* __restrict__ lsm_out,
    float* __restrict__ ei_out, int n_ee, int n_lsm, int n_ei) {
    int b = blockIdx.x;
    int tid = threadIdx.x;
    if (b < COUNT_BLOCKS) {
        int e = b * 256 + tid;
        if (e < N_EDGES) atomicAdd(&g_deg[ei[N_EDGES + e]], 1);
    } else if (b < COUNT_BLOCKS + EMBED_BLOCKS) {
        __shared__ float sW[256];
        __shared__ float sb[16];
        sW[tid] = Wn[tid];
        if (tid < 16) sb[tid] = bn[tid];
        __syncthreads();
        int n = (b - COUNT_BLOCKS) * 256 + tid;
        if (n >= N_NODES) return;
        float xi[16];
        const float4* xp = (const float4*)(x + (size_t)n * 16);
#pragma unroll
        for (int q = 0; q < 4; q++) {
            float4 v = xp[q];
            xi[4*q] = v.x; xi[4*q+1] = v.y; xi[4*q+2] = v.z; xi[4*q+3] = v.w;
        }
        float o[16];
#pragma unroll
        for (int d = 0; d < 16; d++) {
            float acc = sb[d];
#pragma unroll
            for (int k = 0; k < 16; k++) acc = fmaf(xi[k], sW[k*16+d], acc);
            o[d] = fmaxf(acc, 0.f);
        }
        float4* op = (float4*)(g_h0 + (size_t)n * 16);
#pragma unroll
        for (int q = 0; q < 4; q++)
            op[q] = make_float4(o[4*q], o[4*q+1], o[4*q+2], o[4*q+3]);
    } else if (b < COUNT_BLOCKS + EMBED_BLOCKS + EE_BLOCKS) {
        __shared__ float sW[256];
        __shared__ float sb[16];
        sW[tid] = We[tid];
        if (tid < 16) sb[tid] = be[tid];
        __syncthreads();
        int e = (b - COUNT_BLOCKS - EMBED_BLOCKS) * 256 + tid;
        if (e >= N_EDGES) return;
        float xi[16];
        const float4* xp = (const float4*)(ea + (size_t)e * 16);
#pragma unroll
        for (int q = 0; q < 4; q++) {
            float4 v = xp[q];
            xi[4*q] = v.x; xi[4*q+1] = v.y; xi[4*q+2] = v.z; xi[4*q+3] = v.w;
        }
        float v[16];
        float m = -1e30f;
#pragma unroll
        for (int d = 0; d < 16; d++) {
            float acc = sb[d];
#pragma unroll
            for (int k = 0; k < 16; k++) acc = fmaf(xi[k], sW[k*16+d], acc);
            v[d] = fmaxf(acc, 0.f);
            m = fmaxf(m, v[d]);
        }
        float s = 0.f;
#pragma unroll
        for (int d = 0; d < 16; d++) s += expf(v[d] - m);
        float ls = m + logf(s);
        if (e < n_ee) {
            float4* eo = (float4*)(ee_out + (size_t)e * 16);
#pragma unroll
            for (int q = 0; q < 4; q++)
                eo[q] = make_float4(v[4*q], v[4*q+1], v[4*q+2], v[4*q+3]);
        }
        if (e < n_lsm) {
            float4* lo = (float4*)(lsm_out + (size_t)e * 16);
#pragma unroll
            for (int q = 0; q < 4; q++)
                lo[q] = make_float4(v[4*q] - ls, v[4*q+1] - ls,
                                    v[4*q+2] - ls, v[4*q+3] - ls);
        }
    } else {
        int i = (b - COUNT_BLOCKS - EMBED_BLOCKS - EE_BLOCKS) * 256 + tid;
        if (i < n_ei) ei_out[i] = (float)ei[i];
    }
}

// ---------------- launch 1: prefix scan --------------------------------------
__global__ void __launch_bounds__(1024) k_scan() {
    __shared__ int sm[1024];
    int t = threadIdx.x;
    int base = t * 20;
    int vals[20];
    int local = 0;
#pragma unroll
    for (int i = 0; i < 20; i++) {
        int idx = base + i;
        vals[i] = (idx < N_NODES) ? g_deg[idx] : 0;
        local += vals[i];
    }
    sm[t] = local;
    __syncthreads();
    for (int off = 1; off < 1024; off <<= 1) {
        int v = (t >= off) ? sm[t - off] : 0;
        __syncthreads();
        sm[t] += v;
        __syncthreads();
    }
    int run = sm[t] - local;
#pragma unroll
    for (int i = 0; i < 20; i++) {
        int idx = base + i;
        if (idx < N_NODES) { g_off[idx] = run; run += vals[i]; g_cursor[idx] = 0; }
    }
    if (t == 0) g_off[N_NODES] = N_EDGES;
}

// ---------------- launch 2: fill sorted edge list -----------------------------
__global__ void k_fill(const int* __restrict__ ei) {
    int e = blockIdx.x * blockDim.x + threadIdx.x;
    if (e < N_EDGES) {
        int d = ei[N_EDGES + e];
        int pos = g_off[d] + atomicAdd(&g_cursor[d], 1);
        g_es[pos] = make_int2(e, ei[e]);
    }
    if (e < N_NODES) g_deg[e] = 0;
}

// ---------------- launch 3: hid (broadcast-LDS layout) + B build -------------
// 1 thread = 1 edge. W1 reads are lane-uniform (broadcast, conflict-free).
// Outputs staged in pitch-33 smem, flushed fully coalesced.
#define HID2_BLOCKS 3125             // 128 edges per block
#define B2_BLOCKS 512                // 4096*16 / 128
__global__ void __launch_bounds__(128) k_prep2(
    const float* __restrict__ ea,
    const float* __restrict__ W1, const float* __restrict__ b1,
    const float* __restrict__ W2) {
    int b = blockIdx.x;
    int tid = threadIdx.x;
    if (b < HID2_BLOCKS) {
        __shared__ float sW1[2048];
        __shared__ float sB1[128];
        __shared__ int   sE[128];
        __shared__ float sOut[128 * 33];
        int p0 = b * 128;
        sE[tid] = g_es[p0 + tid].x;
        for (int i = tid; i < 2048; i += 128) sW1[i] = W1[i];
        sB1[tid] = b1[tid];
        __syncthreads();

        float a[16];
        {
            const float4* ap = (const float4*)(ea + (size_t)sE[tid] * 16);
            float4 a0 = ap[0], a1 = ap[1], a2 = ap[2], a3 = ap[3];
            a[0]=a0.x; a[1]=a0.y; a[2]=a0.z; a[3]=a0.w;
            a[4]=a1.x; a[5]=a1.y; a[6]=a1.z; a[7]=a1.w;
            a[8]=a2.x; a[9]=a2.y; a[10]=a2.z; a[11]=a2.w;
            a[12]=a3.x; a[13]=a3.y; a[14]=a3.z; a[15]=a3.w;
        }

#pragma unroll
        for (int c = 0; c < 4; c++) {
            float o[32];
#pragma unroll
            for (int j = 0; j < 32; j++) o[j] = sB1[c*32 + j];
#pragma unroll
            for (int q = 0; q < 16; q++) {
                float av = a[q];
                const float* wr = &sW1[q*128 + c*32];   // lane-uniform address
#pragma unroll
                for (int j = 0; j < 32; j++) o[j] = fmaf(av, wr[j], o[j]);
            }
#pragma unroll
            for (int j = 0; j < 32; j++)
                sOut[tid*33 + j] = fmaxf(o[j], 0.f);    // bank (tid+j)%32: clean
            __syncthreads();
            // coalesced flush: 128 edges x 32 floats
#pragma unroll
            for (int i = 0; i < 32; i++) {
                int idx = i * 128 + tid;
                int e = idx >> 5, j = idx & 31;
                g_hid[(size_t)(p0 + e) * 128 + c*32 + j] = sOut[e*33 + j];
            }
            __syncthreads();
        }
    } else {
        int idx = (b - HID2_BLOCKS) * 128 + tid;
        int kj = idx >> 4, d = idx & 15;
        float v;
        if (kj < 2048) {
            int k = kj >> 4, j = kj & 15;
            v = W2[(size_t)k * 512 + (16 + j) * 16 + d];
        } else {
            int m = kj - 2048;
            int k = m >> 4, r = m & 15;
            v = W2[(size_t)k * 512 + r * 16 + d];
        }
        g_B[idx] = v;
    }
}

// ---------------- edge pass: streaming hid, pipelined -------------------------
#define EP_SMEM (8 * 32 * 68 * 4)
__global__ void __launch_bounds__(256, 2) k_edge_pass(int sin) {
    extern __shared__ float st[];
    const float* hin = (sin == 0) ? g_h0 : g_h1;
    int tid = threadIdx.x, wid = tid >> 5, l = tid & 31;
    int n = blockIdx.x * 8 + wid;

    int start = g_off[n], end = g_off[n + 1];

    ull T[4][8];
#pragma unroll
    for (int kk = 0; kk < 4; kk++)
#pragma unroll
        for (int q = 0; q < 8; q++) T[kk][q] = 0ull;
    ull Hs[8];
#pragma unroll
    for (int q = 0; q < 8; q++) Hs[q] = 0ull;
    float hs0 = 0.f, hs1 = 0.f, hs2 = 0.f, hs3 = 0.f;

    if (start < end) {
        int last = end - 1;
        float4 hidC = *(const float4*)(g_hid + (size_t)start * 128 + 4*l);
        int2 esC = g_es[start];
        const ulonglong2* hp = (const ulonglong2*)(hin + (size_t)esC.y * 16);
        ulonglong2 ha = hp[0], hb = hp[1], hc = hp[2], hd = hp[3];
        ull hC[8] = {ha.x, ha.y, hb.x, hb.y, hc.x, hc.y, hd.x, hd.y};

        for (int pos = start; pos < end; pos++) {
            int pn = pos + 1 <= last ? pos + 1 : last;
            float4 hidN = *(const float4*)(g_hid + (size_t)pn * 128 + 4*l);
            int2 esN = g_es[pn];
            const ulonglong2* hp2 = (const ulonglong2*)(hin + (size_t)esN.y * 16);
            ulonglong2 na = hp2[0], nb = hp2[1], nc = hp2[2], nd = hp2[3];
            float4 hd4 = hidC;
#pragma unroll
            for (int q = 0; q < 8; q++) Hs[q] = add2(Hs[q], hC[q]);
            hs0 += hd4.x; hs1 += hd4.y; hs2 += hd4.z; hs3 += hd4.w;
            ull p0 = pack2(hd4.x, hd4.x), pq1 = pack2(hd4.y, hd4.y);
            ull pq2 = pack2(hd4.z, hd4.z), pq3 = pack2(hd4.w, hd4.w);
#pragma unroll
            for (int q = 0; q < 8; q++) {
                T[0][q] = fma2(p0, hC[q], T[0][q]);
                T[1][q] = fma2(pq1, hC[q], T[1][q]);
                T[2][q] = fma2(pq2, hC[q], T[2][q]);
                T[3][q] = fma2(pq3, hC[q], T[3][q]);
            }
            hidC = hidN;
            hC[0] = na.x; hC[1] = na.y; hC[2] = nb.x; hC[3] = nb.y;
            hC[4] = nc.x; hC[5] = nc.y; hC[6] = nd.x; hC[7] = nd.y;
        }
    }

    // write T via warp-local smem transpose (coalesced)
    float* W = st + wid * (32 * 68) + l * 68;
#pragma unroll
    for (int kk = 0; kk < 4; kk++) {
        float t[16];
#pragma unroll
        for (int q = 0; q < 8; q++) unpack2(T[kk][q], t[2*q], t[2*q+1]);
#pragma unroll
        for (int f = 0; f < 4; f++)
            *(float4*)&W[kk*16 + 4*f] = make_float4(t[4*f], t[4*f+1], t[4*f+2], t[4*f+3]);
    }
    __syncwarp();
    float* Wbase = st + wid * (32 * 68);
    float* Trow = g_S + (size_t)n * KT;
#pragma unroll
    for (int s = 0; s < 16; s++) {
        int idx = s * 128 + 4 * l;
        float4 v = *(float4*)&Wbase[(idx >> 6) * 68 + (idx & 63)];
        *(float4*)&Trow[idx] = v;
    }
    *(float4*)&g_Hsum[(size_t)n * 128 + 4*l] = make_float4(hs0, hs1, hs2, hs3);
    if (l == 0) {
#pragma unroll
        for (int q = 0; q < 8; q++) {
            float a, b; unpack2(Hs[q], a, b);
            g_HsJ[n * 16 + 2*q]     = a;
            g_HsJ[n * 16 + 2*q + 1] = b;
        }
    }
}

// ---------------- epilogue: seed hout with non-GEMM terms --------------------
__global__ void k_epi(int sin, int sout, float* ext,
                      const float* __restrict__ root,
                      const float* __restrict__ b2,
                      const float* __restrict__ bias) {
    __shared__ float sR[256];
    __shared__ float sB2[512];
    __shared__ float sBi[16];
    const float* hin = pick_cbuf(sin, ext);
    float* hout = pick_buf(sout, ext);
    int tid = threadIdx.x;
    sR[tid] = root[tid];
    sB2[tid] = b2[tid];
    sB2[256 + tid] = b2[256 + tid];
    if (tid < 16) sBi[tid] = bias[tid];
    __syncthreads();
    int n = blockIdx.x * 256 + tid;
    if (n >= N_NODES) return;
    float h[16], hs[16];
    const float4* hp = (const float4*)(hin + (size_t)n * 16);
    const float4* sp = (const float4*)(g_HsJ + (size_t)n * 16);
#pragma unroll
    for (int q = 0; q < 4; q++) {
        float4 a = hp[q]; h[4*q] = a.x; h[4*q+1] = a.y; h[4*q+2] = a.z; h[4*q+3] = a.w;
        float4 b = sp[q]; hs[4*q] = b.x; hs[4*q+1] = b.y; hs[4*q+2] = b.z; hs[4*q+3] = b.w;
    }
    float dg = (float)(g_off[n+1] - g_off[n]);
    float o[16];
#pragma unroll
    for (int d = 0; d < 16; d++) o[d] = sBi[d];
#pragma unroll
    for (int r = 0; r < 16; r++) {
        float hr = h[r], hdg = h[r] * dg, hj = hs[r];
#pragma unroll
        for (int d = 0; d < 16; d++) {
            o[d] = fmaf(hr, sR[r*16+d], o[d]);
            o[d] = fmaf(hdg, sB2[r*16+d], o[d]);
            o[d] = fmaf(hj, sB2[256 + r*16+d], o[d]);
        }
    }
    float4* op = (float4*)(hout + (size_t)n * 16);
#pragma unroll
    for (int q = 0; q < 4; q++)
        op[q] = make_float4(o[4*q], o[4*q+1], o[4*q+2], o[4*q+3]);
}

// ---------------- GEMM: hout += [T | synth(Hsum⊗h)] @ B ----------------------
#define GT 256
#define SA_P 129
__global__ void __launch_bounds__(GT) k_gemm(int sin, int sout, float* ext) {
    __shared__ __align__(16) float sA[64 * SA_P];
    __shared__ __align__(16) float sB[64 * 16];
    const float* hin = pick_cbuf(sin, ext);
    float* hout = pick_buf(sout, ext);
    int tid = threadIdx.x;
    int n0 = blockIdx.x * 128;
    int ks = blockIdx.y;
    int nn = tid & 127, half = tid >> 7;
    ull acc[4] = {0ull, 0ull, 0ull, 0ull};

    float4 r[8];
    float4 rb;
    auto load_chunk = [&](int c) {
        int k0 = c * 64;
#pragma unroll
        for (int j = 0; j < 8; j++) {
            int i = tid + j * 256;
            int an = i >> 4, q = i & 15;
            int gn = n0 + an;
            float4 v = make_float4(0.f, 0.f, 0.f, 0.f);
            if (gn < N_NODES) {
                if (c < 32) {
                    v = *(const float4*)(g_S + (size_t)gn * KT + k0 + 4*q);
                } else {
                    int m = k0 - 2048 + 4*q;
                    float hsv = g_Hsum[(size_t)gn * 128 + (m >> 4)];
                    float4 h4 = ((const float4*)(hin + (size_t)gn * 16))[(m & 15) >> 2];
                    v = make_float4(hsv*h4.x, hsv*h4.y, hsv*h4.z, hsv*h4.w);
                }
            }
            r[j] = v;
        }
        rb = ((const float4*)(g_B + (size_t)k0 * 16))[tid];
    };

    load_chunk(ks * 8);
    for (int ci = 0; ci < 8; ci++) {
        __syncthreads();
#pragma unroll
        for (int j = 0; j < 8; j++) {
            int i = tid + j * 256;
            int an = i >> 4, q = i & 15;
            sA[(4*q + 0) * SA_P + an] = r[j].x;
            sA[(4*q + 1) * SA_P + an] = r[j].y;
            sA[(4*q + 2) * SA_P + an] = r[j].z;
            sA[(4*q + 3) * SA_P + an] = r[j].w;
        }
        ((float4*)sB)[tid] = rb;
        __syncthreads();
        if (ci < 7) load_chunk(ks * 8 + ci + 1);
#pragma unroll 8
        for (int k = 0; k < 64; k++) {
            float a = sA[k * SA_P + nn];
            ull a2 = pack2(a, a);
            ulonglong2 b01 = *(const ulonglong2*)&sB[k * 16 + 8 * half];
            ulonglong2 b23 = *(const ulonglong2*)&sB[k * 16 + 8 * half + 4];
            acc[0] = fma2(a2, b01.x, acc[0]);
            acc[1] = fma2(a2, b01.y, acc[1]);
            acc[2] = fma2(a2, b23.x, acc[2]);
            acc[3] = fma2(a2, b23.y, acc[3]);
        }
    }

    int n = n0 + nn;
    if (n < N_NODES) {
        float o[8];
        unpack2(acc[0], o[0], o[1]);
        unpack2(acc[1], o[2], o[3]);
        unpack2(acc[2], o[4], o[5]);
        unpack2(acc[3], o[6], o[7]);
        float* dst = hout + (size_t)n * 16 + 8 * half;
#pragma unroll
        for (int j = 0; j < 8; j++) atomicAdd(dst + j, o[j]);
    }
}

// ---------------- launch -------------------------------------------------------
extern "C" void kernel_launch(void* const* d_in, const int* in_sizes, int n_in,
                              void* d_out, int out_size) {
    const float* x     = (const float*)d_in[0];
    const int*   ei    = (const int*)d_in[1];
    const float* ea    = (const float*)d_in[2];
    const float* Wn    = (const float*)d_in[3];
    const float* bn    = (const float*)d_in[4];
    const float* We    = (const float*)d_in[5];
    const float* be    = (const float*)d_in[6];
    const float* W1    = (const float*)d_in[7];
    const float* b1    = (const float*)d_in[8];
    const float* W2    = (const float*)d_in[9];
    const float* b2    = (const float*)d_in[10];
    const float* root1 = (const float*)d_in[11];
    const float* bias1 = (const float*)d_in[12];
    const float* root2 = (const float*)d_in[13];
    const float* bias2 = (const float*)d_in[14];

    float* out = (float*)d_out;
    size_t cap = (size_t)out_size;

    size_t ei_slots = (cap == 13120000) ? 0 : 2ull * N_EDGES;
    size_t off_h   = 0;
    size_t off_ei  = off_h + (size_t)N_NODES * 16;
    size_t off_ee  = off_ei + ei_slots;
    size_t off_lsm = off_ee + (size_t)N_EDGES * 16;
    auto avail = [&](size_t off) -> size_t { return off < cap ? cap - off : 0; };

    float* out_h   = out + off_h;
    float* out_ei  = out + off_ei;
    float* out_ee  = out + off_ee;
    float* out_lsm = out + off_lsm;

    bool h_fits = avail(off_h) >= (size_t)N_NODES * 16;
    int  n_ei   = ei_slots ? (int)min((size_t)(2 * N_EDGES), avail(off_ei)) : 0;
    int  n_ee   = (int)min((size_t)N_EDGES, avail(off_ee) / 16);
    int  n_lsm  = (int)min((size_t)N_EDGES, avail(off_lsm) / 16);
    int  sout2  = h_fits ? 2 : 0;

    cudaFuncSetAttribute(k_edge_pass, cudaFuncAttributeMaxDynamicSharedMemorySize,
                         EP_SMEM);

    // 0: fused front: degree count + node embed + edge embed/lsm + ei copy
    k_front<<<FRONT_BLOCKS, 256>>>(ei, x, Wn, bn, ea, We, be,
                                   out_ee, out_lsm, out_ei, n_ee, n_lsm, n_ei);
    // 1: prefix scan (re-zeros g_cursor)
    k_scan<<<1, 1024>>>();
    // 2: fill sorted edge list (re-zeros g_deg)
    k_fill<<<COUNT_BLOCKS, 256>>>(ei);
    // 3: hid (broadcast-LDS) + B build   [profiled]
    k_prep2<<<HID2_BLOCKS + B2_BLOCKS, 128>>>(ea, W1, b1, W2);

    dim3 gg((N_NODES + 127) / 128, 8);
    // layer 1
    k_edge_pass<<<N_NODES / 8, 256, EP_SMEM>>>(0);
    k_epi<<<(N_NODES + 255) / 256, 256>>>(0, 1, out_h, root1, b2, bias1);
    k_gemm<<<gg, GT>>>(0, 1, out_h);
    // layer 2
    k_edge_pass<<<N_NODES / 8, 256, EP_SMEM>>>(1);
    k_epi<<<(N_NODES + 255) / 256, 256>>>(1, sout2, out_h, root2, b2, bias2);
    k_gemm<<<gg, GT>>>(1, sout2, out_h);
}

// round 14
// speedup vs baseline: 1.6359x; 1.2078x over previous
#include <cuda_runtime.h>
#include <math.h>

#define N_NODES 20000
#define N_EDGES 400000
typedef unsigned long long ull;

// ---------------- device globals --------------------------------------------
__device__ float g_hid[(size_t)N_EDGES * 128];   // hid in DST-SORTED order
__device__ float g_B[4096 * 16];                 // permuted W2
__device__ float g_h0[N_NODES * 16];
__device__ float g_h1[N_NODES * 16];
__device__ int   g_deg[N_NODES];
__device__ int   g_cursor[N_NODES];
__device__ int   g_off[N_NODES + 1];
__device__ int2  g_es[N_EDGES];                  // (edge id, src) sorted by dst

__device__ __forceinline__ float* pick_buf(int s, float* ext) {
    if (s == 0) return g_h0;
    if (s == 1) return g_h1;
    return ext;
}

// ---------------- f32x2 helpers ----------------------------------------------
__device__ __forceinline__ ull pack2(float a, float b) {
    ull r; asm("mov.b64 %0, {%1, %2};" : "=l"(r) : "f"(a), "f"(b)); return r;
}
__device__ __forceinline__ void unpack2(ull v, float& a, float& b) {
    asm("mov.b64 {%0, %1}, %2;" : "=f"(a), "=f"(b) : "l"(v));
}
__device__ __forceinline__ ull fma2(ull a, ull b, ull c) {
    ull d; asm("fma.rn.f32x2 %0, %1, %2, %3;" : "=l"(d) : "l"(a), "l"(b), "l"(c));
    return d;
}
__device__ __forceinline__ ull add2(ull a, ull b) {
    ull d; asm("add.rn.f32x2 %0, %1, %2;" : "=l"(d) : "l"(a), "l"(b)); return d;
}

// ---------------- launch 0: fused front (count/embed/edge-embed/ei) ----------
#define COUNT_BLOCKS 1563
#define EMBED_BLOCKS 79
#define EE_BLOCKS 1563
#define EIC_BLOCKS 3125
#define FRONT_BLOCKS (COUNT_BLOCKS + EMBED_BLOCKS + EE_BLOCKS + EIC_BLOCKS)

__global__ void __launch_bounds__(256) k_front(
    const int* __restrict__ ei, const float* __restrict__ x,
    const float* __restrict__ Wn, const float* __restrict__ bn,
    const float* __restrict__ ea, const float* __restrict__ We,
    const float* __restrict__ be,
    float* __restrict__ ee_out, float* __restrict__ lsm_out,
    float* __restrict__ ei_out, int n_ee, int n_lsm, int n_ei) {
    int b = blockIdx.x;
    int tid = threadIdx.x;
    if (b < COUNT_BLOCKS) {
        int e = b * 256 + tid;
        if (e < N_EDGES) atomicAdd(&g_deg[ei[N_EDGES + e]], 1);
    } else if (b < COUNT_BLOCKS + EMBED_BLOCKS) {
        __shared__ float sW[256];
        __shared__ float sb[16];
        sW[tid] = Wn[tid];
        if (tid < 16) sb[tid] = bn[tid];
        __syncthreads();
        int n = (b - COUNT_BLOCKS) * 256 + tid;
        if (n >= N_NODES) return;
        float xi[16];
        const float4* xp = (const float4*)(x + (size_t)n * 16);
#pragma unroll
        for (int q = 0; q < 4; q++) {
            float4 v = xp[q];
            xi[4*q] = v.x; xi[4*q+1] = v.y; xi[4*q+2] = v.z; xi[4*q+3] = v.w;
        }
        float o[16];
#pragma unroll
        for (int d = 0; d < 16; d++) {
            float acc = sb[d];
#pragma unroll
            for (int k = 0; k < 16; k++) acc = fmaf(xi[k], sW[k*16+d], acc);
            o[d] = fmaxf(acc, 0.f);
        }
        float4* op = (float4*)(g_h0 + (size_t)n * 16);
#pragma unroll
        for (int q = 0; q < 4; q++)
            op[q] = make_float4(o[4*q], o[4*q+1], o[4*q+2], o[4*q+3]);
    } else if (b < COUNT_BLOCKS + EMBED_BLOCKS + EE_BLOCKS) {
        __shared__ float sW[256];
        __shared__ float sb[16];
        sW[tid] = We[tid];
        if (tid < 16) sb[tid] = be[tid];
        __syncthreads();
        int e = (b - COUNT_BLOCKS - EMBED_BLOCKS) * 256 + tid;
        if (e >= N_EDGES) return;
        float xi[16];
        const float4* xp = (const float4*)(ea + (size_t)e * 16);
#pragma unroll
        for (int q = 0; q < 4; q++) {
            float4 v = xp[q];
            xi[4*q] = v.x; xi[4*q+1] = v.y; xi[4*q+2] = v.z; xi[4*q+3] = v.w;
        }
        float v[16];
        float m = -1e30f;
#pragma unroll
        for (int d = 0; d < 16; d++) {
            float acc = sb[d];
#pragma unroll
            for (int k = 0; k < 16; k++) acc = fmaf(xi[k], sW[k*16+d], acc);
            v[d] = fmaxf(acc, 0.f);
            m = fmaxf(m, v[d]);
        }
        float s = 0.f;
#pragma unroll
        for (int d = 0; d < 16; d++) s += expf(v[d] - m);
        float ls = m + logf(s);
        if (e < n_ee) {
            float4* eo = (float4*)(ee_out + (size_t)e * 16);
#pragma unroll
            for (int q = 0; q < 4; q++)
                eo[q] = make_float4(v[4*q], v[4*q+1], v[4*q+2], v[4*q+3]);
        }
        if (e < n_lsm) {
            float4* lo = (float4*)(lsm_out + (size_t)e * 16);
#pragma unroll
            for (int q = 0; q < 4; q++)
                lo[q] = make_float4(v[4*q] - ls, v[4*q+1] - ls,
                                    v[4*q+2] - ls, v[4*q+3] - ls);
        }
    } else {
        int i = (b - COUNT_BLOCKS - EMBED_BLOCKS - EE_BLOCKS) * 256 + tid;
        if (i < n_ei) ei_out[i] = (float)ei[i];
    }
}

// ---------------- launch 1: prefix scan --------------------------------------
__global__ void __launch_bounds__(1024) k_scan() {
    __shared__ int sm[1024];
    int t = threadIdx.x;
    int base = t * 20;
    int vals[20];
    int local = 0;
#pragma unroll
    for (int i = 0; i < 20; i++) {
        int idx = base + i;
        vals[i] = (idx < N_NODES) ? g_deg[idx] : 0;
        local += vals[i];
    }
    sm[t] = local;
    __syncthreads();
    for (int off = 1; off < 1024; off <<= 1) {
        int v = (t >= off) ? sm[t - off] : 0;
        __syncthreads();
        sm[t] += v;
        __syncthreads();
    }
    int run = sm[t] - local;
#pragma unroll
    for (int i = 0; i < 20; i++) {
        int idx = base + i;
        if (idx < N_NODES) { g_off[idx] = run; run += vals[i]; g_cursor[idx] = 0; }
    }
    if (t == 0) g_off[N_NODES] = N_EDGES;
}

// ---------------- launch 2: fill sorted edge list -----------------------------
__global__ void k_fill(const int* __restrict__ ei) {
    int e = blockIdx.x * blockDim.x + threadIdx.x;
    if (e < N_EDGES) {
        int d = ei[N_EDGES + e];
        int pos = g_off[d] + atomicAdd(&g_cursor[d], 1);
        g_es[pos] = make_int2(e, ei[e]);
    }
    if (e < N_NODES) g_deg[e] = 0;
}

// ---------------- launch 3: hid (broadcast-LDS) + B build --------------------
#define HID2_BLOCKS 3125
#define B2_BLOCKS 512
__global__ void __launch_bounds__(128) k_prep2(
    const float* __restrict__ ea,
    const float* __restrict__ W1, const float* __restrict__ b1,
    const float* __restrict__ W2) {
    int b = blockIdx.x;
    int tid = threadIdx.x;
    if (b < HID2_BLOCKS) {
        __shared__ float sW1[2048];
        __shared__ float sB1[128];
        __shared__ int   sE[128];
        __shared__ float sOut[128 * 33];
        int p0 = b * 128;
        sE[tid] = g_es[p0 + tid].x;
        for (int i = tid; i < 2048; i += 128) sW1[i] = W1[i];
        sB1[tid] = b1[tid];
        __syncthreads();

        float a[16];
        {
            const float4* ap = (const float4*)(ea + (size_t)sE[tid] * 16);
            float4 a0 = ap[0], a1 = ap[1], a2 = ap[2], a3 = ap[3];
            a[0]=a0.x; a[1]=a0.y; a[2]=a0.z; a[3]=a0.w;
            a[4]=a1.x; a[5]=a1.y; a[6]=a1.z; a[7]=a1.w;
            a[8]=a2.x; a[9]=a2.y; a[10]=a2.z; a[11]=a2.w;
            a[12]=a3.x; a[13]=a3.y; a[14]=a3.z; a[15]=a3.w;
        }

#pragma unroll
        for (int c = 0; c < 4; c++) {
            float o[32];
#pragma unroll
            for (int j = 0; j < 32; j++) o[j] = sB1[c*32 + j];
#pragma unroll
            for (int q = 0; q < 16; q++) {
                float av = a[q];
                const float* wr = &sW1[q*128 + c*32];
#pragma unroll
                for (int j = 0; j < 32; j++) o[j] = fmaf(av, wr[j], o[j]);
            }
#pragma unroll
            for (int j = 0; j < 32; j++)
                sOut[tid*33 + j] = fmaxf(o[j], 0.f);
            __syncthreads();
#pragma unroll
            for (int i = 0; i < 32; i++) {
                int idx = i * 128 + tid;
                int e = idx >> 5, j = idx & 31;
                g_hid[(size_t)(p0 + e) * 128 + c*32 + j] = sOut[e*33 + j];
            }
            __syncthreads();
        }
    } else {
        int idx = (b - HID2_BLOCKS) * 128 + tid;
        int kj = idx >> 4, d = idx & 15;
        float v;
        if (kj < 2048) {
            int k = kj >> 4, j = kj & 15;
            v = W2[(size_t)k * 512 + (16 + j) * 16 + d];
        } else {
            int m = kj - 2048;
            int k = m >> 4, r = m & 15;
            v = W2[(size_t)k * 512 + r * 16 + d];
        }
        g_B[idx] = v;
    }
}

// ---------------- fused conv: edge loop + in-smem contraction ----------------
// smem float offsets:
#define ST 0                          // 8 * 2180  (T transpose, pitch 68, buf pad +4)
#define SHSUM (8*2180)                // 8 * 132
#define SHX (SHSUM + 8*132)           // 8 * 17    (h of own node)
#define SHS (SHX + 8*17)              // 8 * 16    (sum of h[src])
#define SPART (SHS + 8*16)            // 16 * 4 * 16
#define SRB (SPART + 1024)            // root 256 | b2 512 | bias 16
#define CV_FLOATS (SRB + 784)
#define CV_SMEM (CV_FLOATS * 4)

__global__ void __launch_bounds__(256, 2) k_conv(
    int sin, int sout, float* ext,
    const float* __restrict__ root, const float* __restrict__ b2,
    const float* __restrict__ bias) {
    extern __shared__ float sm[];
    const float* hin = (sin == 0) ? g_h0 : g_h1;
    float* hout = pick_buf(sout, ext);
    int tid = threadIdx.x, wid = tid >> 5, l = tid & 31;
    int n = blockIdx.x * 8 + wid;

    // stage root/b2/bias
    for (int i = tid; i < 784; i += 256) {
        float v = (i < 256) ? root[i] : (i < 768 ? b2[i - 256] : bias[i - 768]);
        sm[SRB + i] = v;
    }

    int start = g_off[n], end = g_off[n + 1];

    // ---- phase 1: edge loop (T, Hs, Hsum in registers) ----
    ull T[4][8];
#pragma unroll
    for (int kk = 0; kk < 4; kk++)
#pragma unroll
        for (int q = 0; q < 8; q++) T[kk][q] = 0ull;
    ull Hs[8];
#pragma unroll
    for (int q = 0; q < 8; q++) Hs[q] = 0ull;
    float hs0 = 0.f, hs1 = 0.f, hs2 = 0.f, hs3 = 0.f;

    if (start < end) {
        int last = end - 1;
        float4 hidC = *(const float4*)(g_hid + (size_t)start * 128 + 4*l);
        int2 esC = g_es[start];
        const ulonglong2* hp = (const ulonglong2*)(hin + (size_t)esC.y * 16);
        ulonglong2 ha = hp[0], hb = hp[1], hc = hp[2], hd = hp[3];
        ull hC[8] = {ha.x, ha.y, hb.x, hb.y, hc.x, hc.y, hd.x, hd.y};

        for (int pos = start; pos < end; pos++) {
            int pn = pos + 1 <= last ? pos + 1 : last;
            float4 hidN = *(const float4*)(g_hid + (size_t)pn * 128 + 4*l);
            int2 esN = g_es[pn];
            const ulonglong2* hp2 = (const ulonglong2*)(hin + (size_t)esN.y * 16);
            ulonglong2 na = hp2[0], nb = hp2[1], nc = hp2[2], nd = hp2[3];
            float4 hd4 = hidC;
#pragma unroll
            for (int q = 0; q < 8; q++) Hs[q] = add2(Hs[q], hC[q]);
            hs0 += hd4.x; hs1 += hd4.y; hs2 += hd4.z; hs3 += hd4.w;
            ull p0 = pack2(hd4.x, hd4.x), pq1 = pack2(hd4.y, hd4.y);
            ull pq2 = pack2(hd4.z, hd4.z), pq3 = pack2(hd4.w, hd4.w);
#pragma unroll
            for (int q = 0; q < 8; q++) {
                T[0][q] = fma2(p0, hC[q], T[0][q]);
                T[1][q] = fma2(pq1, hC[q], T[1][q]);
                T[2][q] = fma2(pq2, hC[q], T[2][q]);
                T[3][q] = fma2(pq3, hC[q], T[3][q]);
            }
            hidC = hidN;
            hC[0] = na.x; hC[1] = na.y; hC[2] = nb.x; hC[3] = nb.y;
            hC[4] = nc.x; hC[5] = nc.y; hC[6] = nd.x; hC[7] = nd.y;
        }
    }

    // ---- stash T / Hsum / h / Hs in smem ----
    float* W = sm + ST + wid * 2180 + l * 68;
#pragma unroll
    for (int kk = 0; kk < 4; kk++) {
        float t[16];
#pragma unroll
        for (int q = 0; q < 8; q++) unpack2(T[kk][q], t[2*q], t[2*q+1]);
#pragma unroll
        for (int f = 0; f < 4; f++)
            *(float4*)&W[kk*16 + 4*f] = make_float4(t[4*f], t[4*f+1], t[4*f+2], t[4*f+3]);
        // Hsum for k = 4l+kk
        float hsv = (kk == 0) ? hs0 : (kk == 1) ? hs1 : (kk == 2) ? hs2 : hs3;
        sm[SHSUM + wid*132 + 4*l + kk] = hsv;
    }
    float hn = (l < 16) ? hin[(size_t)n * 16 + l] : 0.f;
    if (l < 16) sm[SHX + wid*17 + l] = hn;
    if (l == 0) {
#pragma unroll
        for (int q = 0; q < 8; q++) {
            float a, b; unpack2(Hs[q], a, b);
            sm[SHS + wid*16 + 2*q]     = a;
            sm[SHS + wid*16 + 2*q + 1] = b;
        }
    }
    __syncthreads();

    // ---- phase 2: contraction out[8][16] += A[8][4096] @ B[4096][16] ----
    // lane: sub = l&1 (node half), p = l>>1 (kj slot). acc: 4 nodes x 8 d-pairs.
    int sub = l & 1, p = l >> 1;
    ull acc[4][8];
#pragma unroll
    for (int nn = 0; nn < 4; nn++)
#pragma unroll
        for (int q = 0; q < 8; q++) acc[nn][q] = 0ull;

    for (int c = wid; c < 32; c += 8) {
        bool synth = (c >= 16);
#pragma unroll
        for (int i = 0; i < 8; i++) {
            int kj = c*128 + i*16 + p;
            const ulonglong2* Bp = (const ulonglong2*)(g_B + (size_t)kj * 16);
            ulonglong2 x0 = Bp[0], x1 = Bp[1], x2 = Bp[2], x3 = Bp[3];
            ull bb[8] = {x0.x, x0.y, x1.x, x1.y, x2.x, x2.y, x3.x, x3.y};
#pragma unroll
            for (int nn = 0; nn < 4; nn++) {
                int nd = sub*4 + nn;
                float tv;
                if (!synth) {
                    tv = sm[ST + nd*2180 + (kj>>6)*68 + (kj&63)];
                } else {
                    int m = kj - 2048;
                    tv = sm[SHSUM + nd*132 + (m>>4)] * sm[SHX + nd*17 + (m&15)];
                }
                ull tp = pack2(tv, tv);
#pragma unroll
                for (int q = 0; q < 8; q++)
                    acc[nn][q] = fma2(tp, bb[q], acc[nn][q]);
            }
        }
    }

    // reduce across the 16 same-sub lanes
#pragma unroll
    for (int off = 2; off <= 16; off <<= 1) {
#pragma unroll
        for (int nn = 0; nn < 4; nn++)
#pragma unroll
            for (int q = 0; q < 8; q++)
                acc[nn][q] = add2(acc[nn][q],
                                  __shfl_xor_sync(0xffffffffu, acc[nn][q], off));
    }
    if (p == 0) {
#pragma unroll
        for (int nn = 0; nn < 4; nn++) {
            float t[16];
#pragma unroll
            for (int q = 0; q < 8; q++) unpack2(acc[nn][q], t[2*q], t[2*q+1]);
            float* dst = sm + SPART + ((wid*2 + sub)*4 + nn)*16;
#pragma unroll
            for (int d = 0; d < 16; d++) dst[d] = t[d];
        }
    }
    __syncthreads();

    // ---- finale: 128 threads = 8 nodes x 16 d ----
    if (tid < 128) {
        int n8 = tid >> 4, d = tid & 15;
        int sub8 = n8 >> 2, nn8 = n8 & 3;
        float v = sm[SRB + 768 + d];
#pragma unroll
        for (int w = 0; w < 8; w++)
            v += sm[SPART + ((w*2 + sub8)*4 + nn8)*16 + d];
        int node = blockIdx.x * 8 + n8;
        float dg = (float)(g_off[node + 1] - g_off[node]);
#pragma unroll
        for (int r = 0; r < 16; r++) {
            float hr = sm[SHX + n8*17 + r];
            v = fmaf(hr, sm[SRB + r*16 + d], v);
            v = fmaf(dg * hr, sm[SRB + 256 + r*16 + d], v);
            v = fmaf(sm[SHS + n8*16 + r], sm[SRB + 512 + r*16 + d], v);
        }
        hout[(size_t)node * 16 + d] = v;
    }
}

// ---------------- launch -------------------------------------------------------
extern "C" void kernel_launch(void* const* d_in, const int* in_sizes, int n_in,
                              void* d_out, int out_size) {
    const float* x     = (const float*)d_in[0];
    const int*   ei    = (const int*)d_in[1];
    const float* ea    = (const float*)d_in[2];
    const float* Wn    = (const float*)d_in[3];
    const float* bn    = (const float*)d_in[4];
    const float* We    = (const float*)d_in[5];
    const float* be    = (const float*)d_in[6];
    const float* W1    = (const float*)d_in[7];
    const float* b1    = (const float*)d_in[8];
    const float* W2    = (const float*)d_in[9];
    const float* b2    = (const float*)d_in[10];
    const float* root1 = (const float*)d_in[11];
    const float* bias1 = (const float*)d_in[12];
    const float* root2 = (const float*)d_in[13];
    const float* bias2 = (const float*)d_in[14];

    float* out = (float*)d_out;
    size_t cap = (size_t)out_size;

    size_t ei_slots = (cap == 13120000) ? 0 : 2ull * N_EDGES;
    size_t off_h   = 0;
    size_t off_ei  = off_h + (size_t)N_NODES * 16;
    size_t off_ee  = off_ei + ei_slots;
    size_t off_lsm = off_ee + (size_t)N_EDGES * 16;
    auto avail = [&](size_t off) -> size_t { return off < cap ? cap - off : 0; };

    float* out_h   = out + off_h;
    float* out_ei  = out + off_ei;
    float* out_ee  = out + off_ee;
    float* out_lsm = out + off_lsm;

    bool h_fits = avail(off_h) >= (size_t)N_NODES * 16;
    int  n_ei   = ei_slots ? (int)min((size_t)(2 * N_EDGES), avail(off_ei)) : 0;
    int  n_ee   = (int)min((size_t)N_EDGES, avail(off_ee) / 16);
    int  n_lsm  = (int)min((size_t)N_EDGES, avail(off_lsm) / 16);
    int  sout2  = h_fits ? 2 : 0;

    cudaFuncSetAttribute(k_conv, cudaFuncAttributeMaxDynamicSharedMemorySize,
                         CV_SMEM);

    // 0: fused front
    k_front<<<FRONT_BLOCKS, 256>>>(ei, x, Wn, bn, ea, We, be,
                                   out_ee, out_lsm, out_ei, n_ee, n_lsm, n_ei);
    // 1: prefix scan
    k_scan<<<1, 1024>>>();
    // 2: fill sorted edge list
    k_fill<<<COUNT_BLOCKS, 256>>>(ei);
    // 3: hid + B build
    k_prep2<<<HID2_BLOCKS + B2_BLOCKS, 128>>>(ea, W1, b1, W2);
    // 4: fused conv layer 1 (g_h0 -> g_h1)
    k_conv<<<N_NODES / 8, 256, CV_SMEM>>>(0, 1, out_h, root1, b2, bias1);
    // 5: fused conv layer 2 (g_h1 -> out_h)
    k_conv<<<N_NODES / 8, 256, CV_SMEM>>>(1, sout2, out_h, root2, b2, bias2);
}

// round 15
// speedup vs baseline: 1.7553x; 1.0730x over previous
#include <cuda_runtime.h>
#include <math.h>

#define N_NODES 20000
#define N_EDGES 400000
typedef unsigned long long ull;

// ---------------- device globals --------------------------------------------
__device__ float g_hid[(size_t)N_EDGES * 128];   // hid in DST-SORTED order
__device__ float g_B[4096 * 16];                 // permuted W2
__device__ float g_h0[N_NODES * 16];
__device__ float g_h1[N_NODES * 16];
__device__ int   g_deg[N_NODES];
__device__ int   g_cursor[N_NODES];
__device__ int   g_off[N_NODES + 1];
__device__ int2  g_es[N_EDGES];                  // (edge id, src) sorted by dst

__device__ __forceinline__ float* pick_buf(int s, float* ext) {
    if (s == 0) return g_h0;
    if (s == 1) return g_h1;
    return ext;
}

// ---------------- f32x2 helpers ----------------------------------------------
__device__ __forceinline__ ull pack2(float a, float b) {
    ull r; asm("mov.b64 %0, {%1, %2};" : "=l"(r) : "f"(a), "f"(b)); return r;
}
__device__ __forceinline__ void unpack2(ull v, float& a, float& b) {
    asm("mov.b64 {%0, %1}, %2;" : "=f"(a), "=f"(b) : "l"(v));
}
__device__ __forceinline__ ull fma2(ull a, ull b, ull c) {
    ull d; asm("fma.rn.f32x2 %0, %1, %2, %3;" : "=l"(d) : "l"(a), "l"(b), "l"(c));
    return d;
}
__device__ __forceinline__ ull add2(ull a, ull b) {
    ull d; asm("add.rn.f32x2 %0, %1, %2;" : "=l"(d) : "l"(a), "l"(b)); return d;
}

// ---------------- launch 0: fused front (count/embed/edge-embed/ei) ----------
#define COUNT_BLOCKS 1563
#define EMBED_BLOCKS 79
#define EE_BLOCKS 1563
#define EIC_BLOCKS 3125
#define FRONT_BLOCKS (COUNT_BLOCKS + EMBED_BLOCKS + EE_BLOCKS + EIC_BLOCKS)

__global__ void __launch_bounds__(256) k_front(
    const int* __restrict__ ei, const float* __restrict__ x,
    const float* __restrict__ Wn, const float* __restrict__ bn,
    const float* __restrict__ ea, const float* __restrict__ We,
    const float* __restrict__ be,
    float* __restrict__ ee_out, float* __restrict__ lsm_out,
    float* __restrict__ ei_out, int n_ee, int n_lsm, int n_ei) {
    int b = blockIdx.x;
    int tid = threadIdx.x;
    if (b < COUNT_BLOCKS) {
        int e = b * 256 + tid;
        if (e < N_EDGES) atomicAdd(&g_deg[ei[N_EDGES + e]], 1);
    } else if (b < COUNT_BLOCKS + EMBED_BLOCKS) {
        __shared__ float sW[256];
        __shared__ float sb[16];
        sW[tid] = Wn[tid];
        if (tid < 16) sb[tid] = bn[tid];
        __syncthreads();
        int n = (b - COUNT_BLOCKS) * 256 + tid;
        if (n >= N_NODES) return;
        float xi[16];
        const float4* xp = (const float4*)(x + (size_t)n * 16);
#pragma unroll
        for (int q = 0; q < 4; q++) {
            float4 v = xp[q];
            xi[4*q] = v.x; xi[4*q+1] = v.y; xi[4*q+2] = v.z; xi[4*q+3] = v.w;
        }
        float o[16];
#pragma unroll
        for (int d = 0; d < 16; d++) {
            float acc = sb[d];
#pragma unroll
            for (int k = 0; k < 16; k++) acc = fmaf(xi[k], sW[k*16+d], acc);
            o[d] = fmaxf(acc, 0.f);
        }
        float4* op = (float4*)(g_h0 + (size_t)n * 16);
#pragma unroll
        for (int q = 0; q < 4; q++)
            op[q] = make_float4(o[4*q], o[4*q+1], o[4*q+2], o[4*q+3]);
    } else if (b < COUNT_BLOCKS + EMBED_BLOCKS + EE_BLOCKS) {
        __shared__ float sW[256];
        __shared__ float sb[16];
        sW[tid] = We[tid];
        if (tid < 16) sb[tid] = be[tid];
        __syncthreads();
        int e = (b - COUNT_BLOCKS - EMBED_BLOCKS) * 256 + tid;
        if (e >= N_EDGES) return;
        float xi[16];
        const float4* xp = (const float4*)(ea + (size_t)e * 16);
#pragma unroll
        for (int q = 0; q < 4; q++) {
            float4 v = xp[q];
            xi[4*q] = v.x; xi[4*q+1] = v.y; xi[4*q+2] = v.z; xi[4*q+3] = v.w;
        }
        float v[16];
        float m = -1e30f;
#pragma unroll
        for (int d = 0; d < 16; d++) {
            float acc = sb[d];
#pragma unroll
            for (int k = 0; k < 16; k++) acc = fmaf(xi[k], sW[k*16+d], acc);
            v[d] = fmaxf(acc, 0.f);
            m = fmaxf(m, v[d]);
        }
        float s = 0.f;
#pragma unroll
        for (int d = 0; d < 16; d++) s += expf(v[d] - m);
        float ls = m + logf(s);
        if (e < n_ee) {
            float4* eo = (float4*)(ee_out + (size_t)e * 16);
#pragma unroll
            for (int q = 0; q < 4; q++)
                eo[q] = make_float4(v[4*q], v[4*q+1], v[4*q+2], v[4*q+3]);
        }
        if (e < n_lsm) {
            float4* lo = (float4*)(lsm_out + (size_t)e * 16);
#pragma unroll
            for (int q = 0; q < 4; q++)
                lo[q] = make_float4(v[4*q] - ls, v[4*q+1] - ls,
                                    v[4*q+2] - ls, v[4*q+3] - ls);
        }
    } else {
        int i = (b - COUNT_BLOCKS - EMBED_BLOCKS - EE_BLOCKS) * 256 + tid;
        if (i < n_ei) ei_out[i] = (float)ei[i];
    }
}

// ---------------- launch 1: prefix scan --------------------------------------
__global__ void __launch_bounds__(1024) k_scan() {
    __shared__ int sm[1024];
    int t = threadIdx.x;
    int base = t * 20;
    int vals[20];
    int local = 0;
#pragma unroll
    for (int i = 0; i < 20; i++) {
        int idx = base + i;
        vals[i] = (idx < N_NODES) ? g_deg[idx] : 0;
        local += vals[i];
    }
    sm[t] = local;
    __syncthreads();
    for (int off = 1; off < 1024; off <<= 1) {
        int v = (t >= off) ? sm[t - off] : 0;
        __syncthreads();
        sm[t] += v;
        __syncthreads();
    }
    int run = sm[t] - local;
#pragma unroll
    for (int i = 0; i < 20; i++) {
        int idx = base + i;
        if (idx < N_NODES) { g_off[idx] = run; run += vals[i]; g_cursor[idx] = 0; }
    }
    if (t == 0) g_off[N_NODES] = N_EDGES;
}

// ---------------- launch 2: fill sorted edge list -----------------------------
__global__ void k_fill(const int* __restrict__ ei) {
    int e = blockIdx.x * blockDim.x + threadIdx.x;
    if (e < N_EDGES) {
        int d = ei[N_EDGES + e];
        int pos = g_off[d] + atomicAdd(&g_cursor[d], 1);
        g_es[pos] = make_int2(e, ei[e]);
    }
    if (e < N_NODES) g_deg[e] = 0;
}

// ---------------- launch 3: hid (broadcast-LDS) + B build --------------------
#define HID2_BLOCKS 3125
#define B2_BLOCKS 512
__global__ void __launch_bounds__(128) k_prep2(
    const float* __restrict__ ea,
    const float* __restrict__ W1, const float* __restrict__ b1,
    const float* __restrict__ W2) {
    int b = blockIdx.x;
    int tid = threadIdx.x;
    if (b < HID2_BLOCKS) {
        __shared__ float sW1[2048];
        __shared__ float sB1[128];
        __shared__ int   sE[128];
        __shared__ float sOut[128 * 33];
        int p0 = b * 128;
        sE[tid] = g_es[p0 + tid].x;
        for (int i = tid; i < 2048; i += 128) sW1[i] = W1[i];
        sB1[tid] = b1[tid];
        __syncthreads();

        float a[16];
        {
            const float4* ap = (const float4*)(ea + (size_t)sE[tid] * 16);
            float4 a0 = ap[0], a1 = ap[1], a2 = ap[2], a3 = ap[3];
            a[0]=a0.x; a[1]=a0.y; a[2]=a0.z; a[3]=a0.w;
            a[4]=a1.x; a[5]=a1.y; a[6]=a1.z; a[7]=a1.w;
            a[8]=a2.x; a[9]=a2.y; a[10]=a2.z; a[11]=a2.w;
            a[12]=a3.x; a[13]=a3.y; a[14]=a3.z; a[15]=a3.w;
        }

#pragma unroll 1
        for (int c = 0; c < 4; c++) {
            float o[32];
#pragma unroll
            for (int j = 0; j < 32; j++) o[j] = sB1[c*32 + j];
#pragma unroll
            for (int q = 0; q < 16; q++) {
                float av = a[q];
                const float* wr = &sW1[q*128 + c*32];
#pragma unroll
                for (int j = 0; j < 32; j++) o[j] = fmaf(av, wr[j], o[j]);
            }
#pragma unroll
            for (int j = 0; j < 32; j++)
                sOut[tid*33 + j] = fmaxf(o[j], 0.f);
            __syncthreads();
#pragma unroll
            for (int i = 0; i < 32; i++) {
                int idx = i * 128 + tid;
                int e = idx >> 5, j = idx & 31;
                g_hid[(size_t)(p0 + e) * 128 + c*32 + j] = sOut[e*33 + j];
            }
            __syncthreads();
        }
    } else {
        int idx = (b - HID2_BLOCKS) * 128 + tid;
        int kj = idx >> 4, d = idx & 15;
        float v;
        if (kj < 2048) {
            int k = kj >> 4, j = kj & 15;
            v = W2[(size_t)k * 512 + (16 + j) * 16 + d];
        } else {
            int m = kj - 2048;
            int k = m >> 4, r = m & 15;
            v = W2[(size_t)k * 512 + r * 16 + d];
        }
        g_B[idx] = v;
    }
}

// ---------------- fused conv: 16 nodes / 512 threads per block ---------------
// smem float offsets:
#define ST 0                           // 16 * 2180 (T transpose, pitch 68)
#define SHSUM (16*2180)                // 16 * 132
#define SHX (SHSUM + 16*132)           // 16 * 17
#define SHS (SHX + 16*17)              // 16 * 16
#define SPART (SHS + 16*16)            // 16 warps * 16 nodes * 16 d
#define SRB (SPART + 4096)             // root 256 | b2 512 | bias 16
#define CV_FLOATS (SRB + 784)
#define CV_SMEM (CV_FLOATS * 4)        // 169,600 B

__global__ void __launch_bounds__(512, 1) k_conv(
    int sin, int sout, float* ext,
    const float* __restrict__ root, const float* __restrict__ b2,
    const float* __restrict__ bias) {
    extern __shared__ float sm[];
    const float* hin = (sin == 0) ? g_h0 : g_h1;
    float* hout = pick_buf(sout, ext);
    int tid = threadIdx.x, wid = tid >> 5, l = tid & 31;
    int n = blockIdx.x * 16 + wid;

    for (int i = tid; i < 784; i += 512) {
        float v = (i < 256) ? root[i] : (i < 768 ? b2[i - 256] : bias[i - 768]);
        sm[SRB + i] = v;
    }

    int start = g_off[n], end = g_off[n + 1];

    // ---- phase 1: edge loop (one warp per node) ----
    ull T[4][8];
#pragma unroll
    for (int kk = 0; kk < 4; kk++)
#pragma unroll
        for (int q = 0; q < 8; q++) T[kk][q] = 0ull;
    ull Hs[8];
#pragma unroll
    for (int q = 0; q < 8; q++) Hs[q] = 0ull;
    float hs0 = 0.f, hs1 = 0.f, hs2 = 0.f, hs3 = 0.f;

    if (start < end) {
        int last = end - 1;
        float4 hidC = *(const float4*)(g_hid + (size_t)start * 128 + 4*l);
        int2 esC = g_es[start];
        const ulonglong2* hp = (const ulonglong2*)(hin + (size_t)esC.y * 16);
        ulonglong2 ha = hp[0], hb = hp[1], hc = hp[2], hd = hp[3];
        ull hC[8] = {ha.x, ha.y, hb.x, hb.y, hc.x, hc.y, hd.x, hd.y};

        for (int pos = start; pos < end; pos++) {
            int pn = pos + 1 <= last ? pos + 1 : last;
            float4 hidN = *(const float4*)(g_hid + (size_t)pn * 128 + 4*l);
            int2 esN = g_es[pn];
            const ulonglong2* hp2 = (const ulonglong2*)(hin + (size_t)esN.y * 16);
            ulonglong2 na = hp2[0], nb = hp2[1], nc = hp2[2], nd = hp2[3];
            float4 hd4 = hidC;
#pragma unroll
            for (int q = 0; q < 8; q++) Hs[q] = add2(Hs[q], hC[q]);
            hs0 += hd4.x; hs1 += hd4.y; hs2 += hd4.z; hs3 += hd4.w;
            ull p0 = pack2(hd4.x, hd4.x), pq1 = pack2(hd4.y, hd4.y);
            ull pq2 = pack2(hd4.z, hd4.z), pq3 = pack2(hd4.w, hd4.w);
#pragma unroll
            for (int q = 0; q < 8; q++) {
                T[0][q] = fma2(p0, hC[q], T[0][q]);
                T[1][q] = fma2(pq1, hC[q], T[1][q]);
                T[2][q] = fma2(pq2, hC[q], T[2][q]);
                T[3][q] = fma2(pq3, hC[q], T[3][q]);
            }
            hidC = hidN;
            hC[0] = na.x; hC[1] = na.y; hC[2] = nb.x; hC[3] = nb.y;
            hC[4] = nc.x; hC[5] = nc.y; hC[6] = nd.x; hC[7] = nd.y;
        }
    }

    // ---- stash T / Hsum / h / Hs in smem ----
    float* W = sm + ST + wid * 2180 + l * 68;
#pragma unroll
    for (int kk = 0; kk < 4; kk++) {
        float t[16];
#pragma unroll
        for (int q = 0; q < 8; q++) unpack2(T[kk][q], t[2*q], t[2*q+1]);
#pragma unroll
        for (int f = 0; f < 4; f++)
            *(float4*)&W[kk*16 + 4*f] = make_float4(t[4*f], t[4*f+1], t[4*f+2], t[4*f+3]);
        float hsv = (kk == 0) ? hs0 : (kk == 1) ? hs1 : (kk == 2) ? hs2 : hs3;
        sm[SHSUM + wid*132 + 4*l + kk] = hsv;
    }
    float hn = (l < 16) ? hin[(size_t)n * 16 + l] : 0.f;
    if (l < 16) sm[SHX + wid*17 + l] = hn;
    if (l == 0) {
#pragma unroll
        for (int q = 0; q < 8; q++) {
            float a, b; unpack2(Hs[q], a, b);
            sm[SHS + wid*16 + 2*q]     = a;
            sm[SHS + wid*16 + 2*q + 1] = b;
        }
    }
    __syncthreads();

    // ---- phase 2: contraction out[16][16] += A[16][4096] @ B[4096][16] ----
    // lane: sub = l&3 (node quarter, 4 nodes), p = l>>2 (kj slot 0..7)
    int sub = l & 3, p = l >> 2;
    ull acc[4][8];
#pragma unroll
    for (int nn = 0; nn < 4; nn++)
#pragma unroll
        for (int q = 0; q < 8; q++) acc[nn][q] = 0ull;

#pragma unroll
    for (int cc = 0; cc < 2; cc++) {
        int c = wid + cc * 16;
        bool synth = (c >= 16);
#pragma unroll
        for (int i = 0; i < 16; i++) {
            int kj = c*128 + i*8 + p;
            const ulonglong2* Bp = (const ulonglong2*)(g_B + (size_t)kj * 16);
            ulonglong2 x0 = Bp[0], x1 = Bp[1], x2 = Bp[2], x3 = Bp[3];
            ull bb[8] = {x0.x, x0.y, x1.x, x1.y, x2.x, x2.y, x3.x, x3.y};
#pragma unroll
            for (int nn = 0; nn < 4; nn++) {
                int nd = sub*4 + nn;
                float tv;
                if (!synth) {
                    tv = sm[ST + nd*2180 + (kj>>6)*68 + (kj&63)];
                } else {
                    int m = kj - 2048;
                    tv = sm[SHSUM + nd*132 + (m>>4)] * sm[SHX + nd*17 + (m&15)];
                }
                ull tp = pack2(tv, tv);
#pragma unroll
                for (int q = 0; q < 8; q++)
                    acc[nn][q] = fma2(tp, bb[q], acc[nn][q]);
            }
        }
    }

    // reduce across the 8 p-lanes (same sub)
#pragma unroll
    for (int off = 4; off <= 16; off <<= 1) {
#pragma unroll
        for (int nn = 0; nn < 4; nn++)
#pragma unroll
            for (int q = 0; q < 8; q++)
                acc[nn][q] = add2(acc[nn][q],
                                  __shfl_xor_sync(0xffffffffu, acc[nn][q], off));
    }
    if (p == 0) {
#pragma unroll
        for (int nn = 0; nn < 4; nn++) {
            float t[16];
#pragma unroll
            for (int q = 0; q < 8; q++) unpack2(acc[nn][q], t[2*q], t[2*q+1]);
            float* dst = sm + SPART + (wid*16 + sub*4 + nn)*16;
#pragma unroll
            for (int d = 0; d < 16; d++) dst[d] = t[d];
        }
    }
    __syncthreads();

    // ---- finale: 256 threads = 16 nodes x 16 d ----
    if (tid < 256) {
        int n16 = tid >> 4, d = tid & 15;
        float v = sm[SRB + 768 + d];
#pragma unroll
        for (int w = 0; w < 16; w++)
            v += sm[SPART + (w*16 + n16)*16 + d];
        int node = blockIdx.x * 16 + n16;
        float dg = (float)(g_off[node + 1] - g_off[node]);
#pragma unroll
        for (int r = 0; r < 16; r++) {
            float hr = sm[SHX + n16*17 + r];
            v = fmaf(hr, sm[SRB + r*16 + d], v);
            v = fmaf(dg * hr, sm[SRB + 256 + r*16 + d], v);
            v = fmaf(sm[SHS + n16*16 + r], sm[SRB + 512 + r*16 + d], v);
        }
        hout[(size_t)node * 16 + d] = v;
    }
}

// ---------------- launch -------------------------------------------------------
extern "C" void kernel_launch(void* const* d_in, const int* in_sizes, int n_in,
                              void* d_out, int out_size) {
    const float* x     = (const float*)d_in[0];
    const int*   ei    = (const int*)d_in[1];
    const float* ea    = (const float*)d_in[2];
    const float* Wn    = (const float*)d_in[3];
    const float* bn    = (const float*)d_in[4];
    const float* We    = (const float*)d_in[5];
    const float* be    = (const float*)d_in[6];
    const float* W1    = (const float*)d_in[7];
    const float* b1    = (const float*)d_in[8];
    const float* W2    = (const float*)d_in[9];
    const float* b2    = (const float*)d_in[10];
    const float* root1 = (const float*)d_in[11];
    const float* bias1 = (const float*)d_in[12];
    const float* root2 = (const float*)d_in[13];
    const float* bias2 = (const float*)d_in[14];

    float* out = (float*)d_out;
    size_t cap = (size_t)out_size;

    size_t ei_slots = (cap == 13120000) ? 0 : 2ull * N_EDGES;
    size_t off_h   = 0;
    size_t off_ei  = off_h + (size_t)N_NODES * 16;
    size_t off_ee  = off_ei + ei_slots;
    size_t off_lsm = off_ee + (size_t)N_EDGES * 16;
    auto avail = [&](size_t off) -> size_t { return off < cap ? cap - off : 0; };

    float* out_h   = out + off_h;
    float* out_ei  = out + off_ei;
    float* out_ee  = out + off_ee;
    float* out_lsm = out + off_lsm;

    bool h_fits = avail(off_h) >= (size_t)N_NODES * 16;
    int  n_ei   = ei_slots ? (int)min((size_t)(2 * N_EDGES), avail(off_ei)) : 0;
    int  n_ee   = (int)min((size_t)N_EDGES, avail(off_ee) / 16);
    int  n_lsm  = (int)min((size_t)N_EDGES, avail(off_lsm) / 16);
    int  sout2  = h_fits ? 2 : 0;

    cudaFuncSetAttribute(k_conv, cudaFuncAttributeMaxDynamicSharedMemorySize,
                         CV_SMEM);

    // 0: fused front
    k_front<<<FRONT_BLOCKS, 256>>>(ei, x, Wn, bn, ea, We, be,
                                   out_ee, out_lsm, out_ei, n_ee, n_lsm, n_ei);
    // 1: prefix scan
    k_scan<<<1, 1024>>>();
    // 2: fill sorted edge list
    k_fill<<<COUNT_BLOCKS, 256>>>(ei);
    // 3: hid + B build
    k_prep2<<<HID2_BLOCKS + B2_BLOCKS, 128>>>(ea, W1, b1, W2);
    // 4: fused conv layer 1 (g_h0 -> g_h1)
    k_conv<<<N_NODES / 16, 512, CV_SMEM>>>(0, 1, out_h, root1, b2, bias1);
    // 5: fused conv layer 2 (g_h1 -> out_h)
    k_conv<<<N_NODES / 16, 512, CV_SMEM>>>(1, sout2, out_h, root2, b2, bias2);
}

// round 16
// speedup vs baseline: 1.7690x; 1.0078x over previous
#include <cuda_runtime.h>
#include <math.h>

#define N_NODES 20000
#define N_EDGES 400000
typedef unsigned long long ull;

// ---------------- device globals --------------------------------------------
__device__ float g_hid[(size_t)N_EDGES * 128];   // hid in DST-SORTED order
__device__ float g_B[4096 * 16];                 // permuted W2
__device__ float g_h0[N_NODES * 16];
__device__ float g_h1[N_NODES * 16];
__device__ int   g_deg[N_NODES];
__device__ int   g_cursor[N_NODES];
__device__ int   g_off[N_NODES + 1];
__device__ int2  g_es[N_EDGES];                  // (edge id, src) sorted by dst

__device__ __forceinline__ float* pick_buf(int s, float* ext) {
    if (s == 0) return g_h0;
    if (s == 1) return g_h1;
    return ext;
}

// ---------------- f32x2 helpers ----------------------------------------------
__device__ __forceinline__ ull pack2(float a, float b) {
    ull r; asm("mov.b64 %0, {%1, %2};" : "=l"(r) : "f"(a), "f"(b)); return r;
}
__device__ __forceinline__ void unpack2(ull v, float& a, float& b) {
    asm("mov.b64 {%0, %1}, %2;" : "=f"(a), "=f"(b) : "l"(v));
}
__device__ __forceinline__ ull fma2(ull a, ull b, ull c) {
    ull d; asm("fma.rn.f32x2 %0, %1, %2, %3;" : "=l"(d) : "l"(a), "l"(b), "l"(c));
    return d;
}
__device__ __forceinline__ ull add2(ull a, ull b) {
    ull d; asm("add.rn.f32x2 %0, %1, %2;" : "=l"(d) : "l"(a), "l"(b)); return d;
}

// ---------------- launch 0: fused front (count/embed/edge-embed/ei) ----------
#define COUNT_BLOCKS 1563
#define EMBED_BLOCKS 79
#define EE_BLOCKS 1563
#define EIC_BLOCKS 3125
#define FRONT_BLOCKS (COUNT_BLOCKS + EMBED_BLOCKS + EE_BLOCKS + EIC_BLOCKS)

__global__ void __launch_bounds__(256) k_front(
    const int* __restrict__ ei, const float* __restrict__ x,
    const float* __restrict__ Wn, const float* __restrict__ bn,
    const float* __restrict__ ea, const float* __restrict__ We,
    const float* __restrict__ be,
    float* __restrict__ ee_out, float* __restrict__ lsm_out,
    float* __restrict__ ei_out, int n_ee, int n_lsm, int n_ei) {
    int b = blockIdx.x;
    int tid = threadIdx.x;
    if (b < COUNT_BLOCKS) {
        int e = b * 256 + tid;
        if (e < N_EDGES) atomicAdd(&g_deg[ei[N_EDGES + e]], 1);
    } else if (b < COUNT_BLOCKS + EMBED_BLOCKS) {
        __shared__ float sW[256];
        __shared__ float sb[16];
        sW[tid] = Wn[tid];
        if (tid < 16) sb[tid] = bn[tid];
        __syncthreads();
        int n = (b - COUNT_BLOCKS) * 256 + tid;
        if (n >= N_NODES) return;
        float xi[16];
        const float4* xp = (const float4*)(x + (size_t)n * 16);
#pragma unroll
        for (int q = 0; q < 4; q++) {
            float4 v = xp[q];
            xi[4*q] = v.x; xi[4*q+1] = v.y; xi[4*q+2] = v.z; xi[4*q+3] = v.w;
        }
        float o[16];
#pragma unroll
        for (int d = 0; d < 16; d++) {
            float acc = sb[d];
#pragma unroll
            for (int k = 0; k < 16; k++) acc = fmaf(xi[k], sW[k*16+d], acc);
            o[d] = fmaxf(acc, 0.f);
        }
        float4* op = (float4*)(g_h0 + (size_t)n * 16);
#pragma unroll
        for (int q = 0; q < 4; q++)
            op[q] = make_float4(o[4*q], o[4*q+1], o[4*q+2], o[4*q+3]);
    } else if (b < COUNT_BLOCKS + EMBED_BLOCKS + EE_BLOCKS) {
        __shared__ float sW[256];
        __shared__ float sb[16];
        sW[tid] = We[tid];
        if (tid < 16) sb[tid] = be[tid];
        __syncthreads();
        int e = (b - COUNT_BLOCKS - EMBED_BLOCKS) * 256 + tid;
        if (e >= N_EDGES) return;
        float xi[16];
        const float4* xp = (const float4*)(ea + (size_t)e * 16);
#pragma unroll
        for (int q = 0; q < 4; q++) {
            float4 v = xp[q];
            xi[4*q] = v.x; xi[4*q+1] = v.y; xi[4*q+2] = v.z; xi[4*q+3] = v.w;
        }
        float v[16];
        float m = -1e30f;
#pragma unroll
        for (int d = 0; d < 16; d++) {
            float acc = sb[d];
#pragma unroll
            for (int k = 0; k < 16; k++) acc = fmaf(xi[k], sW[k*16+d], acc);
            v[d] = fmaxf(acc, 0.f);
            m = fmaxf(m, v[d]);
        }
        float s = 0.f;
#pragma unroll
        for (int d = 0; d < 16; d++) s += expf(v[d] - m);
        float ls = m + logf(s);
        if (e < n_ee) {
            float4* eo = (float4*)(ee_out + (size_t)e * 16);
#pragma unroll
            for (int q = 0; q < 4; q++)
                eo[q] = make_float4(v[4*q], v[4*q+1], v[4*q+2], v[4*q+3]);
        }
        if (e < n_lsm) {
            float4* lo = (float4*)(lsm_out + (size_t)e * 16);
#pragma unroll
            for (int q = 0; q < 4; q++)
                lo[q] = make_float4(v[4*q] - ls, v[4*q+1] - ls,
                                    v[4*q+2] - ls, v[4*q+3] - ls);
        }
    } else {
        int i = (b - COUNT_BLOCKS - EMBED_BLOCKS - EE_BLOCKS) * 256 + tid;
        if (i < n_ei) ei_out[i] = (float)ei[i];
    }
}

// ---------------- launch 1: prefix scan --------------------------------------
__global__ void __launch_bounds__(1024) k_scan() {
    __shared__ int sm[1024];
    int t = threadIdx.x;
    int base = t * 20;
    int vals[20];
    int local = 0;
#pragma unroll
    for (int i = 0; i < 20; i++) {
        int idx = base + i;
        vals[i] = (idx < N_NODES) ? g_deg[idx] : 0;
        local += vals[i];
    }
    sm[t] = local;
    __syncthreads();
    for (int off = 1; off < 1024; off <<= 1) {
        int v = (t >= off) ? sm[t - off] : 0;
        __syncthreads();
        sm[t] += v;
        __syncthreads();
    }
    int run = sm[t] - local;
#pragma unroll
    for (int i = 0; i < 20; i++) {
        int idx = base + i;
        if (idx < N_NODES) { g_off[idx] = run; run += vals[i]; g_cursor[idx] = 0; }
    }
    if (t == 0) g_off[N_NODES] = N_EDGES;
}

// ---------------- launch 2: fused fill + hid + B build -----------------------
// block owns 128 ORIGINAL edges: computes sorted pos, writes g_es, computes
// hid (coalesced ea reads, broadcast W1) and stores rows at pos (scattered
// 128B chunks — measured free in R12).
#define FH_BLOCKS 3125
#define B2_BLOCKS 512
__global__ void __launch_bounds__(128) k_fillhid(
    const int* __restrict__ ei, const float* __restrict__ ea,
    const float* __restrict__ W1, const float* __restrict__ b1,
    const float* __restrict__ W2) {
    int b = blockIdx.x;
    int tid = threadIdx.x;
    if (b < FH_BLOCKS) {
        __shared__ float sW1[2048];
        __shared__ float sB1[128];
        __shared__ int   sPos[128];
        __shared__ float sOut[128 * 33];
        int e = b * 128 + tid;

        // fill: compute sorted position
        int d = ei[N_EDGES + e];
        int s = ei[e];
        int pos = g_off[d] + atomicAdd(&g_cursor[d], 1);
        g_es[pos] = make_int2(e, s);
        sPos[tid] = pos;
        if (e < N_NODES) g_deg[e] = 0;   // re-zero for next replay

        for (int i = tid; i < 2048; i += 128) sW1[i] = W1[i];
        sB1[tid] = b1[tid];

        // hid inputs: coalesced ea row
        float a[16];
        {
            const float4* ap = (const float4*)(ea + (size_t)e * 16);
            float4 a0 = ap[0], a1 = ap[1], a2 = ap[2], a3 = ap[3];
            a[0]=a0.x; a[1]=a0.y; a[2]=a0.z; a[3]=a0.w;
            a[4]=a1.x; a[5]=a1.y; a[6]=a1.z; a[7]=a1.w;
            a[8]=a2.x; a[9]=a2.y; a[10]=a2.z; a[11]=a2.w;
            a[12]=a3.x; a[13]=a3.y; a[14]=a3.z; a[15]=a3.w;
        }
        __syncthreads();

#pragma unroll 1
        for (int c = 0; c < 4; c++) {
            float o[32];
#pragma unroll
            for (int j = 0; j < 32; j++) o[j] = sB1[c*32 + j];
#pragma unroll
            for (int q = 0; q < 16; q++) {
                float av = a[q];
                const float* wr = &sW1[q*128 + c*32];   // lane-uniform
#pragma unroll
                for (int j = 0; j < 32; j++) o[j] = fmaf(av, wr[j], o[j]);
            }
#pragma unroll
            for (int j = 0; j < 32; j++)
                sOut[tid*33 + j] = fmaxf(o[j], 0.f);
            __syncthreads();
            // flush: each warp writes 8 rows x 128B chunks (row = sorted pos)
#pragma unroll
            for (int i = 0; i < 32; i++) {
                int idx = i * 128 + tid;
                int el = idx >> 5, j = idx & 31;
                g_hid[(size_t)sPos[el] * 128 + c*32 + j] = sOut[el*33 + j];
            }
            __syncthreads();
        }
    } else {
        int idx = (b - FH_BLOCKS) * 128 + tid;
        int kj = idx >> 4, dd = idx & 15;
        float v;
        if (kj < 2048) {
            int k = kj >> 4, j = kj & 15;
            v = W2[(size_t)k * 512 + (16 + j) * 16 + dd];
        } else {
            int m = kj - 2048;
            int k = m >> 4, r = m & 15;
            v = W2[(size_t)k * 512 + r * 16 + dd];
        }
        g_B[idx] = v;
    }
}

// ---------------- fused conv: 16 nodes / 512 threads per block ---------------
#define ST 0                           // 16 * 2180 (T transpose, pitch 68)
#define SHSUM (16*2180)                // 16 * 132
#define SHX (SHSUM + 16*132)           // 16 * 17
#define SHS (SHX + 16*17)              // 16 * 16
#define SPART (SHS + 16*16)            // 16 warps * 16 nodes * 16 d
#define SRB (SPART + 4096)             // root 256 | b2 512 | bias 16
#define CV_FLOATS (SRB + 784)
#define CV_SMEM (CV_FLOATS * 4)        // 169,600 B

__global__ void __launch_bounds__(512, 1) k_conv(
    int sin, int sout, float* ext,
    const float* __restrict__ root, const float* __restrict__ b2,
    const float* __restrict__ bias) {
    extern __shared__ float sm[];
    const float* hin = (sin == 0) ? g_h0 : g_h1;
    float* hout = pick_buf(sout, ext);
    int tid = threadIdx.x, wid = tid >> 5, l = tid & 31;
    int n = blockIdx.x * 16 + wid;

    for (int i = tid; i < 784; i += 512) {
        float v = (i < 256) ? root[i] : (i < 768 ? b2[i - 256] : bias[i - 768]);
        sm[SRB + i] = v;
    }

    int start = g_off[n], end = g_off[n + 1];

    // ---- phase 1: edge loop (one warp per node, 2-deep index pipeline) ----
    ull T[4][8];
#pragma unroll
    for (int kk = 0; kk < 4; kk++)
#pragma unroll
        for (int q = 0; q < 8; q++) T[kk][q] = 0ull;
    ull Hs[8];
#pragma unroll
    for (int q = 0; q < 8; q++) Hs[q] = 0ull;
    float hs0 = 0.f, hs1 = 0.f, hs2 = 0.f, hs3 = 0.f;

    if (start < end) {
        int last = end - 1;
        int2 esC = g_es[start];
        int p1 = start + 1 <= last ? start + 1 : last;
        int2 esF = g_es[p1];                     // index for pos+1 (prefetched)
        float4 hidC = *(const float4*)(g_hid + (size_t)start * 128 + 4*l);
        const ulonglong2* hp = (const ulonglong2*)(hin + (size_t)esC.y * 16);
        ulonglong2 ha = hp[0], hb = hp[1], hc = hp[2], hd = hp[3];
        ull hC[8] = {ha.x, ha.y, hb.x, hb.y, hc.x, hc.y, hd.x, hd.y};

        for (int pos = start; pos < end; pos++) {
            int p2 = pos + 2 <= last ? pos + 2 : last;
            int2 esF2 = g_es[p2];                // prefetch index for pos+2
            int pn = pos + 1 <= last ? pos + 1 : last;
            float4 hidN = *(const float4*)(g_hid + (size_t)pn * 128 + 4*l);
            const ulonglong2* hp2 = (const ulonglong2*)(hin + (size_t)esF.y * 16);
            ulonglong2 na = hp2[0], nb = hp2[1], nc = hp2[2], nd = hp2[3];
            float4 hd4 = hidC;
#pragma unroll
            for (int q = 0; q < 8; q++) Hs[q] = add2(Hs[q], hC[q]);
            hs0 += hd4.x; hs1 += hd4.y; hs2 += hd4.z; hs3 += hd4.w;
            ull p0 = pack2(hd4.x, hd4.x), pq1 = pack2(hd4.y, hd4.y);
            ull pq2 = pack2(hd4.z, hd4.z), pq3 = pack2(hd4.w, hd4.w);
#pragma unroll
            for (int q = 0; q < 8; q++) {
                T[0][q] = fma2(p0, hC[q], T[0][q]);
                T[1][q] = fma2(pq1, hC[q], T[1][q]);
                T[2][q] = fma2(pq2, hC[q], T[2][q]);
                T[3][q] = fma2(pq3, hC[q], T[3][q]);
            }
            hidC = hidN;
            hC[0] = na.x; hC[1] = na.y; hC[2] = nb.x; hC[3] = nb.y;
            hC[4] = nc.x; hC[5] = nc.y; hC[6] = nd.x; hC[7] = nd.y;
            esF = esF2;
        }
    }

    // ---- stash T / Hsum / h / Hs in smem ----
    float* W = sm + ST + wid * 2180 + l * 68;
#pragma unroll
    for (int kk = 0; kk < 4; kk++) {
        float t[16];
#pragma unroll
        for (int q = 0; q < 8; q++) unpack2(T[kk][q], t[2*q], t[2*q+1]);
#pragma unroll
        for (int f = 0; f < 4; f++)
            *(float4*)&W[kk*16 + 4*f] = make_float4(t[4*f], t[4*f+1], t[4*f+2], t[4*f+3]);
        float hsv = (kk == 0) ? hs0 : (kk == 1) ? hs1 : (kk == 2) ? hs2 : hs3;
        sm[SHSUM + wid*132 + 4*l + kk] = hsv;
    }
    float hn = (l < 16) ? hin[(size_t)n * 16 + l] : 0.f;
    if (l < 16) sm[SHX + wid*17 + l] = hn;
    if (l == 0) {
#pragma unroll
        for (int q = 0; q < 8; q++) {
            float a, b; unpack2(Hs[q], a, b);
            sm[SHS + wid*16 + 2*q]     = a;
            sm[SHS + wid*16 + 2*q + 1] = b;
        }
    }
    __syncthreads();

    // ---- phase 2: contraction out[16][16] += A[16][4096] @ B[4096][16] ----
    int sub = l & 3, p = l >> 2;
    ull acc[4][8];
#pragma unroll
    for (int nn = 0; nn < 4; nn++)
#pragma unroll
        for (int q = 0; q < 8; q++) acc[nn][q] = 0ull;

#pragma unroll
    for (int cc = 0; cc < 2; cc++) {
        int c = wid + cc * 16;
        bool synth = (c >= 16);
#pragma unroll
        for (int i = 0; i < 16; i++) {
            int kj = c*128 + i*8 + p;
            const ulonglong2* Bp = (const ulonglong2*)(g_B + (size_t)kj * 16);
            ulonglong2 x0 = Bp[0], x1 = Bp[1], x2 = Bp[2], x3 = Bp[3];
            ull bb[8] = {x0.x, x0.y, x1.x, x1.y, x2.x, x2.y, x3.x, x3.y};
#pragma unroll
            for (int nn = 0; nn < 4; nn++) {
                int nd = sub*4 + nn;
                float tv;
                if (!synth) {
                    tv = sm[ST + nd*2180 + (kj>>6)*68 + (kj&63)];
                } else {
                    int m = kj - 2048;
                    tv = sm[SHSUM + nd*132 + (m>>4)] * sm[SHX + nd*17 + (m&15)];
                }
                ull tp = pack2(tv, tv);
#pragma unroll
                for (int q = 0; q < 8; q++)
                    acc[nn][q] = fma2(tp, bb[q], acc[nn][q]);
            }
        }
    }

#pragma unroll
    for (int off = 4; off <= 16; off <<= 1) {
#pragma unroll
        for (int nn = 0; nn < 4; nn++)
#pragma unroll
            for (int q = 0; q < 8; q++)
                acc[nn][q] = add2(acc[nn][q],
                                  __shfl_xor_sync(0xffffffffu, acc[nn][q], off));
    }
    if (p == 0) {
#pragma unroll
        for (int nn = 0; nn < 4; nn++) {
            float t[16];
#pragma unroll
            for (int q = 0; q < 8; q++) unpack2(acc[nn][q], t[2*q], t[2*q+1]);
            float* dst = sm + SPART + (wid*16 + sub*4 + nn)*16;
#pragma unroll
            for (int d = 0; d < 16; d++) dst[d] = t[d];
        }
    }
    __syncthreads();

    // ---- finale: 256 threads = 16 nodes x 16 d ----
    if (tid < 256) {
        int n16 = tid >> 4, d = tid & 15;
        float v = sm[SRB + 768 + d];
#pragma unroll
        for (int w = 0; w < 16; w++)
            v += sm[SPART + (w*16 + n16)*16 + d];
        int node = blockIdx.x * 16 + n16;
        float dg = (float)(g_off[node + 1] - g_off[node]);
#pragma unroll
        for (int r = 0; r < 16; r++) {
            float hr = sm[SHX + n16*17 + r];
            v = fmaf(hr, sm[SRB + r*16 + d], v);
            v = fmaf(dg * hr, sm[SRB + 256 + r*16 + d], v);
            v = fmaf(sm[SHS + n16*16 + r], sm[SRB + 512 + r*16 + d], v);
        }
        hout[(size_t)node * 16 + d] = v;
    }
}

// ---------------- launch -------------------------------------------------------
extern "C" void kernel_launch(void* const* d_in, const int* in_sizes, int n_in,
                              void* d_out, int out_size) {
    const float* x     = (const float*)d_in[0];
    const int*   ei    = (const int*)d_in[1];
    const float* ea    = (const float*)d_in[2];
    const float* Wn    = (const float*)d_in[3];
    const float* bn    = (const float*)d_in[4];
    const float* We    = (const float*)d_in[5];
    const float* be    = (const float*)d_in[6];
    const float* W1    = (const float*)d_in[7];
    const float* b1    = (const float*)d_in[8];
    const float* W2    = (const float*)d_in[9];
    const float* b2    = (const float*)d_in[10];
    const float* root1 = (const float*)d_in[11];
    const float* bias1 = (const float*)d_in[12];
    const float* root2 = (const float*)d_in[13];
    const float* bias2 = (const float*)d_in[14];

    float* out = (float*)d_out;
    size_t cap = (size_t)out_size;

    size_t ei_slots = (cap == 13120000) ? 0 : 2ull * N_EDGES;
    size_t off_h   = 0;
    size_t off_ei  = off_h + (size_t)N_NODES * 16;
    size_t off_ee  = off_ei + ei_slots;
    size_t off_lsm = off_ee + (size_t)N_EDGES * 16;
    auto avail = [&](size_t off) -> size_t { return off < cap ? cap - off : 0; };

    float* out_h   = out + off_h;
    float* out_ei  = out + off_ei;
    float* out_ee  = out + off_ee;
    float* out_lsm = out + off_lsm;

    bool h_fits = avail(off_h) >= (size_t)N_NODES * 16;
    int  n_ei   = ei_slots ? (int)min((size_t)(2 * N_EDGES), avail(off_ei)) : 0;
    int  n_ee   = (int)min((size_t)N_EDGES, avail(off_ee) / 16);
    int  n_lsm  = (int)min((size_t)N_EDGES, avail(off_lsm) / 16);
    int  sout2  = h_fits ? 2 : 0;

    cudaFuncSetAttribute(k_conv, cudaFuncAttributeMaxDynamicSharedMemorySize,
                         CV_SMEM);

    // 0: fused front
    k_front<<<FRONT_BLOCKS, 256>>>(ei, x, Wn, bn, ea, We, be,
                                   out_ee, out_lsm, out_ei, n_ee, n_lsm, n_ei);
    // 1: prefix scan (re-zeros g_cursor)
    k_scan<<<1, 1024>>>();
    // 2: fused fill + hid + B build (re-zeros g_deg)
    k_fillhid<<<FH_BLOCKS + B2_BLOCKS, 128>>>(ei, ea, W1, b1, W2);
    // 3: fused conv layer 1 (g_h0 -> g_h1)   [profiled]
    k_conv<<<N_NODES / 16, 512, CV_SMEM>>>(0, 1, out_h, root1, b2, bias1);
    // 4: fused conv layer 2 (g_h1 -> out_h)
    k_conv<<<N_NODES / 16, 512, CV_SMEM>>>(1, sout2, out_h, root2, b2, bias2);
}

// round 17
// speedup vs baseline: 2.2423x; 1.2676x over previous
#include <cuda_runtime.h>
#include <math.h>

#define N_NODES 20000
#define N_EDGES 400000
typedef unsigned long long ull;

// ---------------- device globals --------------------------------------------
__device__ float g_hid[(size_t)N_EDGES * 128];   // hid in DST-SORTED order
__device__ float g_B[4096 * 16];                 // permuted W2
__device__ float g_h0[N_NODES * 16];
__device__ float g_h1[N_NODES * 16];
__device__ int   g_deg[N_NODES];
__device__ int   g_cursor[N_NODES];
__device__ int   g_off[N_NODES + 1];
__device__ int2  g_es[N_EDGES];                  // (edge id, src) sorted by dst

__device__ __forceinline__ float* pick_buf(int s, float* ext) {
    if (s == 0) return g_h0;
    if (s == 1) return g_h1;
    return ext;
}

// ---------------- f32x2 / cp.async helpers -----------------------------------
__device__ __forceinline__ ull pack2(float a, float b) {
    ull r; asm("mov.b64 %0, {%1, %2};" : "=l"(r) : "f"(a), "f"(b)); return r;
}
__device__ __forceinline__ void unpack2(ull v, float& a, float& b) {
    asm("mov.b64 {%0, %1}, %2;" : "=f"(a), "=f"(b) : "l"(v));
}
__device__ __forceinline__ ull fma2(ull a, ull b, ull c) {
    ull d; asm("fma.rn.f32x2 %0, %1, %2, %3;" : "=l"(d) : "l"(a), "l"(b), "l"(c));
    return d;
}
__device__ __forceinline__ ull add2(ull a, ull b) {
    ull d; asm("add.rn.f32x2 %0, %1, %2;" : "=l"(d) : "l"(a), "l"(b)); return d;
}
__device__ __forceinline__ void cpa16(unsigned int dst, const void* src) {
    asm volatile("cp.async.ca.shared.global [%0], [%1], 16;\n" :: "r"(dst), "l"(src));
}
#define CP_COMMIT() asm volatile("cp.async.commit_group;\n" ::: "memory")
#define CP_WAIT1()  asm volatile("cp.async.wait_group 1;\n" ::: "memory")
#define CP_WAIT0()  asm volatile("cp.async.wait_group 0;\n" ::: "memory")

// ---------------- launch 0: fused front (count/embed/edge-embed/ei) ----------
#define COUNT_BLOCKS 1563
#define EMBED_BLOCKS 79
#define EE_BLOCKS 1563
#define EIC_BLOCKS 3125
#define FRONT_BLOCKS (COUNT_BLOCKS + EMBED_BLOCKS + EE_BLOCKS + EIC_BLOCKS)

__global__ void __launch_bounds__(256) k_front(
    const int* __restrict__ ei, const float* __restrict__ x,
    const float* __restrict__ Wn, const float* __restrict__ bn,
    const float* __restrict__ ea, const float* __restrict__ We,
    const float* __restrict__ be,
    float* __restrict__ ee_out, float* __restrict__ lsm_out,
    float* __restrict__ ei_out, int n_ee, int n_lsm, int n_ei) {
    int b = blockIdx.x;
    int tid = threadIdx.x;
    if (b < COUNT_BLOCKS) {
        int e = b * 256 + tid;
        if (e < N_EDGES) atomicAdd(&g_deg[ei[N_EDGES + e]], 1);
    } else if (b < COUNT_BLOCKS + EMBED_BLOCKS) {
        __shared__ float sW[256];
        __shared__ float sb[16];
        sW[tid] = Wn[tid];
        if (tid < 16) sb[tid] = bn[tid];
        __syncthreads();
        int n = (b - COUNT_BLOCKS) * 256 + tid;
        if (n >= N_NODES) return;
        float xi[16];
        const float4* xp = (const float4*)(x + (size_t)n * 16);
#pragma unroll
        for (int q = 0; q < 4; q++) {
            float4 v = xp[q];
            xi[4*q] = v.x; xi[4*q+1] = v.y; xi[4*q+2] = v.z; xi[4*q+3] = v.w;
        }
        float o[16];
#pragma unroll
        for (int d = 0; d < 16; d++) {
            float acc = sb[d];
#pragma unroll
            for (int k = 0; k < 16; k++) acc = fmaf(xi[k], sW[k*16+d], acc);
            o[d] = fmaxf(acc, 0.f);
        }
        float4* op = (float4*)(g_h0 + (size_t)n * 16);
#pragma unroll
        for (int q = 0; q < 4; q++)
            op[q] = make_float4(o[4*q], o[4*q+1], o[4*q+2], o[4*q+3]);
    } else if (b < COUNT_BLOCKS + EMBED_BLOCKS + EE_BLOCKS) {
        __shared__ float sW[256];
        __shared__ float sb[16];
        sW[tid] = We[tid];
        if (tid < 16) sb[tid] = be[tid];
        __syncthreads();
        int e = (b - COUNT_BLOCKS - EMBED_BLOCKS) * 256 + tid;
        if (e >= N_EDGES) return;
        float xi[16];
        const float4* xp = (const float4*)(ea + (size_t)e * 16);
#pragma unroll
        for (int q = 0; q < 4; q++) {
            float4 v = xp[q];
            xi[4*q] = v.x; xi[4*q+1] = v.y; xi[4*q+2] = v.z; xi[4*q+3] = v.w;
        }
        float v[16];
        float m = -1e30f;
#pragma unroll
        for (int d = 0; d < 16; d++) {
            float acc = sb[d];
#pragma unroll
            for (int k = 0; k < 16; k++) acc = fmaf(xi[k], sW[k*16+d], acc);
            v[d] = fmaxf(acc, 0.f);
            m = fmaxf(m, v[d]);
        }
        float s = 0.f;
#pragma unroll
        for (int d = 0; d < 16; d++) s += expf(v[d] - m);
        float ls = m + logf(s);
        if (e < n_ee) {
            float4* eo = (float4*)(ee_out + (size_t)e * 16);
#pragma unroll
            for (int q = 0; q < 4; q++)
                eo[q] = make_float4(v[4*q], v[4*q+1], v[4*q+2], v[4*q+3]);
        }
        if (e < n_lsm) {
            float4* lo = (float4*)(lsm_out + (size_t)e * 16);
#pragma unroll
            for (int q = 0; q < 4; q++)
                lo[q] = make_float4(v[4*q] - ls, v[4*q+1] - ls,
                                    v[4*q+2] - ls, v[4*q+3] - ls);
        }
    } else {
        int i = (b - COUNT_BLOCKS - EMBED_BLOCKS - EE_BLOCKS) * 256 + tid;
        if (i < n_ei) ei_out[i] = (float)ei[i];
    }
}

// ---------------- launch 1: prefix scan --------------------------------------
__global__ void __launch_bounds__(1024) k_scan() {
    __shared__ int sm[1024];
    int t = threadIdx.x;
    int base = t * 20;
    int vals[20];
    int local = 0;
#pragma unroll
    for (int i = 0; i < 20; i++) {
        int idx = base + i;
        vals[i] = (idx < N_NODES) ? g_deg[idx] : 0;
        local += vals[i];
    }
    sm[t] = local;
    __syncthreads();
    for (int off = 1; off < 1024; off <<= 1) {
        int v = (t >= off) ? sm[t - off] : 0;
        __syncthreads();
        sm[t] += v;
        __syncthreads();
    }
    int run = sm[t] - local;
#pragma unroll
    for (int i = 0; i < 20; i++) {
        int idx = base + i;
        if (idx < N_NODES) { g_off[idx] = run; run += vals[i]; g_cursor[idx] = 0; }
    }
    if (t == 0) g_off[N_NODES] = N_EDGES;
}

// ---------------- launch 2: fused fill + hid + B build -----------------------
#define FH_BLOCKS 3125
#define B2_BLOCKS 512
__global__ void __launch_bounds__(128) k_fillhid(
    const int* __restrict__ ei, const float* __restrict__ ea,
    const float* __restrict__ W1, const float* __restrict__ b1,
    const float* __restrict__ W2) {
    int b = blockIdx.x;
    int tid = threadIdx.x;
    if (b < FH_BLOCKS) {
        __shared__ float sW1[2048];
        __shared__ float sB1[128];
        __shared__ int   sPos[128];
        __shared__ float sOut[128 * 33];
        int e = b * 128 + tid;

        int d = ei[N_EDGES + e];
        int s = ei[e];
        int pos = g_off[d] + atomicAdd(&g_cursor[d], 1);
        g_es[pos] = make_int2(e, s);
        sPos[tid] = pos;
        if (e < N_NODES) g_deg[e] = 0;

        for (int i = tid; i < 2048; i += 128) sW1[i] = W1[i];
        sB1[tid] = b1[tid];

        float a[16];
        {
            const float4* ap = (const float4*)(ea + (size_t)e * 16);
            float4 a0 = ap[0], a1 = ap[1], a2 = ap[2], a3 = ap[3];
            a[0]=a0.x; a[1]=a0.y; a[2]=a0.z; a[3]=a0.w;
            a[4]=a1.x; a[5]=a1.y; a[6]=a1.z; a[7]=a1.w;
            a[8]=a2.x; a[9]=a2.y; a[10]=a2.z; a[11]=a2.w;
            a[12]=a3.x; a[13]=a3.y; a[14]=a3.z; a[15]=a3.w;
        }
        __syncthreads();

#pragma unroll 1
        for (int c = 0; c < 4; c++) {
            float o[32];
#pragma unroll
            for (int j = 0; j < 32; j++) o[j] = sB1[c*32 + j];
#pragma unroll
            for (int q = 0; q < 16; q++) {
                float av = a[q];
                const float* wr = &sW1[q*128 + c*32];
#pragma unroll
                for (int j = 0; j < 32; j++) o[j] = fmaf(av, wr[j], o[j]);
            }
#pragma unroll
            for (int j = 0; j < 32; j++)
                sOut[tid*33 + j] = fmaxf(o[j], 0.f);
            __syncthreads();
#pragma unroll
            for (int i = 0; i < 32; i++) {
                int idx = i * 128 + tid;
                int el = idx >> 5, j = idx & 31;
                g_hid[(size_t)sPos[el] * 128 + c*32 + j] = sOut[el*33 + j];
            }
            __syncthreads();
        }
    } else {
        int idx = (b - FH_BLOCKS) * 128 + tid;
        int kj = idx >> 4, dd = idx & 15;
        float v;
        if (kj < 2048) {
            int k = kj >> 4, j = kj & 15;
            v = W2[(size_t)k * 512 + (16 + j) * 16 + dd];
        } else {
            int m = kj - 2048;
            int k = m >> 4, r = m & 15;
            v = W2[(size_t)k * 512 + r * 16 + dd];
        }
        g_B[idx] = v;
    }
}

// ---------------- fused conv: 16 nodes / 512 threads, cp.async ring ----------
#define ST 0                           // 16 * 2180 (T transpose pitch 68; ring reuses head)
#define SHSUM (16*2180)
#define SHX (SHSUM + 16*132)
#define SHS (SHX + 16*17)
#define SPART (SHS + 16*16)
#define SRB (SPART + 4096)
#define CV_FLOATS (SRB + 784)
#define CV_SMEM (CV_FLOATS * 4)        // 169,600 B
#define SLOT_F 144                     // 576 B per edge slot: hid 512B + h 64B

__global__ void __launch_bounds__(512, 1) k_conv(
    int sin, int sout, float* ext,
    const float* __restrict__ root, const float* __restrict__ b2,
    const float* __restrict__ bias) {
    extern __shared__ float sm[];
    const float* hin = (sin == 0) ? g_h0 : g_h1;
    float* hout = pick_buf(sout, ext);
    int tid = threadIdx.x, wid = tid >> 5, l = tid & 31;
    int n = blockIdx.x * 16 + wid;

    for (int i = tid; i < 784; i += 512) {
        float v = (i < 256) ? root[i] : (i < 768 ? b2[i - 256] : bias[i - 768]);
        sm[SRB + i] = v;
    }

    int start = g_off[n], end = g_off[n + 1];

    // ---- phase 1: edge loop via 2-chunk x 4-edge cp.async ring ----
    float* ringp = sm + ST + wid * 2180;                    // warp's slice head
    unsigned int ringb = (unsigned int)__cvta_generic_to_shared(ringp);

    ull T[4][8];
#pragma unroll
    for (int kk = 0; kk < 4; kk++)
#pragma unroll
        for (int q = 0; q < 8; q++) T[kk][q] = 0ull;
    ull Hs[8];
#pragma unroll
    for (int q = 0; q < 8; q++) Hs[q] = 0ull;
    float hs0 = 0.f, hs1 = 0.f, hs2 = 0.f, hs3 = 0.f;

    if (start < end) {
        // issue chunk c into buffer (c&1)
        auto issue = [&](int c) {
#pragma unroll
            for (int u = 0; u < 4; u++) {
                int pos = start + c * 4 + u;
                if (pos < end) {
                    unsigned int slot = ringb + (((c & 1) * 4 + u) * SLOT_F) * 4;
                    int2 es = g_es[pos];
                    cpa16(slot + l * 16,
                          (const char*)g_hid + ((size_t)pos * 128 + 4 * l) * 4);
                    if (l < 4)
                        cpa16(slot + 512 + l * 16,
                              (const char*)hin + ((size_t)es.y * 16 + 4 * l) * 4);
                }
            }
            CP_COMMIT();
        };
        issue(0);
        issue(1);
        int nch = (end - start + 3) >> 2;
        for (int c = 0; c < nch; c++) {
            CP_WAIT1();
            __syncwarp();
#pragma unroll
            for (int u = 0; u < 4; u++) {
                int pos = start + c * 4 + u;
                if (pos < end) {
                    const float* slotp = ringp + ((c & 1) * 4 + u) * SLOT_F;
                    float4 hd4 = *(const float4*)(slotp + 4 * l);
                    const ulonglong2* hp = (const ulonglong2*)(slotp + 128);
                    ulonglong2 ha = hp[0], hb = hp[1], hc = hp[2], hdq = hp[3];
                    ull hC[8] = {ha.x, ha.y, hb.x, hb.y, hc.x, hc.y, hdq.x, hdq.y};
#pragma unroll
                    for (int q = 0; q < 8; q++) Hs[q] = add2(Hs[q], hC[q]);
                    hs0 += hd4.x; hs1 += hd4.y; hs2 += hd4.z; hs3 += hd4.w;
                    ull p0 = pack2(hd4.x, hd4.x), pq1 = pack2(hd4.y, hd4.y);
                    ull pq2 = pack2(hd4.z, hd4.z), pq3 = pack2(hd4.w, hd4.w);
#pragma unroll
                    for (int q = 0; q < 8; q++) {
                        T[0][q] = fma2(p0, hC[q], T[0][q]);
                        T[1][q] = fma2(pq1, hC[q], T[1][q]);
                        T[2][q] = fma2(pq2, hC[q], T[2][q]);
                        T[3][q] = fma2(pq3, hC[q], T[3][q]);
                    }
                }
            }
            issue(c + 2);
        }
        CP_WAIT0();
        __syncwarp();
    }

    // ---- stash T / Hsum / h / Hs in smem (overwrites ring; drained above) ----
    float* W = sm + ST + wid * 2180 + l * 68;
#pragma unroll
    for (int kk = 0; kk < 4; kk++) {
        float t[16];
#pragma unroll
        for (int q = 0; q < 8; q++) unpack2(T[kk][q], t[2*q], t[2*q+1]);
#pragma unroll
        for (int f = 0; f < 4; f++)
            *(float4*)&W[kk*16 + 4*f] = make_float4(t[4*f], t[4*f+1], t[4*f+2], t[4*f+3]);
        float hsv = (kk == 0) ? hs0 : (kk == 1) ? hs1 : (kk == 2) ? hs2 : hs3;
        sm[SHSUM + wid*132 + 4*l + kk] = hsv;
    }
    float hn = (l < 16) ? hin[(size_t)n * 16 + l] : 0.f;
    if (l < 16) sm[SHX + wid*17 + l] = hn;
    if (l == 0) {
#pragma unroll
        for (int q = 0; q < 8; q++) {
            float a, b; unpack2(Hs[q], a, b);
            sm[SHS + wid*16 + 2*q]     = a;
            sm[SHS + wid*16 + 2*q + 1] = b;
        }
    }
    __syncthreads();

    // ---- phase 2: contraction out[16][16] += A[16][4096] @ B[4096][16] ----
    int sub = l & 3, p = l >> 2;
    ull acc[4][8];
#pragma unroll
    for (int nn = 0; nn < 4; nn++)
#pragma unroll
        for (int q = 0; q < 8; q++) acc[nn][q] = 0ull;

#pragma unroll
    for (int cc = 0; cc < 2; cc++) {
        int c = wid + cc * 16;
        bool synth = (c >= 16);
#pragma unroll
        for (int i = 0; i < 16; i++) {
            int kj = c*128 + i*8 + p;
            const ulonglong2* Bp = (const ulonglong2*)(g_B + (size_t)kj * 16);
            ulonglong2 x0 = Bp[0], x1 = Bp[1], x2 = Bp[2], x3 = Bp[3];
            ull bb[8] = {x0.x, x0.y, x1.x, x1.y, x2.x, x2.y, x3.x, x3.y};
#pragma unroll
            for (int nn = 0; nn < 4; nn++) {
                int nd = sub*4 + nn;
                float tv;
                if (!synth) {
                    tv = sm[ST + nd*2180 + (kj>>6)*68 + (kj&63)];
                } else {
                    int m = kj - 2048;
                    tv = sm[SHSUM + nd*132 + (m>>4)] * sm[SHX + nd*17 + (m&15)];
                }
                ull tp = pack2(tv, tv);
#pragma unroll
                for (int q = 0; q < 8; q++)
                    acc[nn][q] = fma2(tp, bb[q], acc[nn][q]);
            }
        }
    }

#pragma unroll
    for (int off = 4; off <= 16; off <<= 1) {
#pragma unroll
        for (int nn = 0; nn < 4; nn++)
#pragma unroll
            for (int q = 0; q < 8; q++)
                acc[nn][q] = add2(acc[nn][q],
                                  __shfl_xor_sync(0xffffffffu, acc[nn][q], off));
    }
    if (p == 0) {
#pragma unroll
        for (int nn = 0; nn < 4; nn++) {
            float t[16];
#pragma unroll
            for (int q = 0; q < 8; q++) unpack2(acc[nn][q], t[2*q], t[2*q+1]);
            float* dst = sm + SPART + (wid*16 + sub*4 + nn)*16;
#pragma unroll
            for (int d = 0; d < 16; d++) dst[d] = t[d];
        }
    }
    __syncthreads();

    // ---- finale: 256 threads = 16 nodes x 16 d ----
    if (tid < 256) {
        int n16 = tid >> 4, d = tid & 15;
        float v = sm[SRB + 768 + d];
#pragma unroll
        for (int w = 0; w < 16; w++)
            v += sm[SPART + (w*16 + n16)*16 + d];
        int node = blockIdx.x * 16 + n16;
        float dg = (float)(g_off[node + 1] - g_off[node]);
#pragma unroll
        for (int r = 0; r < 16; r++) {
            float hr = sm[SHX + n16*17 + r];
            v = fmaf(hr, sm[SRB + r*16 + d], v);
            v = fmaf(dg * hr, sm[SRB + 256 + r*16 + d], v);
            v = fmaf(sm[SHS + n16*16 + r], sm[SRB + 512 + r*16 + d], v);
        }
        hout[(size_t)node * 16 + d] = v;
    }
}

// ---------------- launch -------------------------------------------------------
extern "C" void kernel_launch(void* const* d_in, const int* in_sizes, int n_in,
                              void* d_out, int out_size) {
    const float* x     = (const float*)d_in[0];
    const int*   ei    = (const int*)d_in[1];
    const float* ea    = (const float*)d_in[2];
    const float* Wn    = (const float*)d_in[3];
    const float* bn    = (const float*)d_in[4];
    const float* We    = (const float*)d_in[5];
    const float* be    = (const float*)d_in[6];
    const float* W1    = (const float*)d_in[7];
    const float* b1    = (const float*)d_in[8];
    const float* W2    = (const float*)d_in[9];
    const float* b2    = (const float*)d_in[10];
    const float* root1 = (const float*)d_in[11];
    const float* bias1 = (const float*)d_in[12];
    const float* root2 = (const float*)d_in[13];
    const float* bias2 = (const float*)d_in[14];

    float* out = (float*)d_out;
    size_t cap = (size_t)out_size;

    size_t ei_slots = (cap == 13120000) ? 0 : 2ull * N_EDGES;
    size_t off_h   = 0;
    size_t off_ei  = off_h + (size_t)N_NODES * 16;
    size_t off_ee  = off_ei + ei_slots;
    size_t off_lsm = off_ee + (size_t)N_EDGES * 16;
    auto avail = [&](size_t off) -> size_t { return off < cap ? cap - off : 0; };

    float* out_h   = out + off_h;
    float* out_ei  = out + off_ei;
    float* out_ee  = out + off_ee;
    float* out_lsm = out + off_lsm;

    bool h_fits = avail(off_h) >= (size_t)N_NODES * 16;
    int  n_ei   = ei_slots ? (int)min((size_t)(2 * N_EDGES), avail(off_ei)) : 0;
    int  n_ee   = (int)min((size_t)N_EDGES, avail(off_ee) / 16);
    int  n_lsm  = (int)min((size_t)N_EDGES, avail(off_lsm) / 16);
    int  sout2  = h_fits ? 2 : 0;

    cudaFuncSetAttribute(k_conv, cudaFuncAttributeMaxDynamicSharedMemorySize,
                         CV_SMEM);

    // 0: fused front
    k_front<<<FRONT_BLOCKS, 256>>>(ei, x, Wn, bn, ea, We, be,
                                   out_ee, out_lsm, out_ei, n_ee, n_lsm, n_ei);
    // 1: prefix scan (re-zeros g_cursor)
    k_scan<<<1, 1024>>>();
    // 2: fused fill + hid + B build (re-zeros g_deg)
    k_fillhid<<<FH_BLOCKS + B2_BLOCKS, 128>>>(ei, ea, W1, b1, W2);
    // 3: fused conv layer 1 (g_h0 -> g_h1)   [profiled]
    k_conv<<<N_NODES / 16, 512, CV_SMEM>>>(0, 1, out_h, root1, b2, bias1);
    // 4: fused conv layer 2 (g_h1 -> out_h)
    k_conv<<<N_NODES / 16, 512, CV_SMEM>>>(1, sout2, out_h, root2, b2, bias2);
}